// round 1
// baseline (speedup 1.0000x reference)
#include <cuda_runtime.h>
#include <math.h>

#define N_NODES 20000
#define N_EDGES 640000
#define HID 128
#define NB 3
#define NGS 47
#define NF 50          // NB + NGS
#define B_GRAPHS 16
#define LOG2F_ 0.69314718055994530942f
#define CUTF 10.0f
#define PI_F 3.14159265358979323846f

// ---------------- scratch (device globals: alloc-free) ----------------
__device__ float g_h  [N_NODES * HID];
__device__ float g_xh [N_NODES * HID];
__device__ float g_agg[N_NODES * HID];
__device__ float g_tmp[N_NODES * HID];
__device__ float g_ew [N_EDGES];
__device__ float g_Cc [N_EDGES];

__device__ __forceinline__ float sspf(float x) {
    // softplus(x) - log(2), numerically safe
    float sp = (x > 15.f) ? x : log1pf(__expf(x));
    return sp - LOG2F_;
}

// ---------------- small kernels ----------------
__global__ void zero_out_kernel(float* out) {
    if (threadIdx.x < B_GRAPHS) out[threadIdx.x] = 0.f;
}

__global__ void embed_kernel(const int* __restrict__ z, const float* __restrict__ emb) {
    int i = blockIdx.x * blockDim.x + threadIdx.x;
    if (i < N_NODES * HID) {
        int n = i >> 7, c = i & 127;
        g_h[i] = emb[z[n] * HID + c];
    }
}

__global__ void zero_agg_kernel() {
    int i = blockIdx.x * blockDim.x + threadIdx.x;
    if (i < N_NODES * HID) g_agg[i] = 0.f;
}

__global__ void edge_pre_kernel(const int* __restrict__ ei, const float* __restrict__ pos) {
    int e = blockIdx.x * blockDim.x + threadIdx.x;
    if (e < N_EDGES) {
        int r = ei[e], c = ei[N_EDGES + e];
        float dx = pos[r * 3 + 0] - pos[c * 3 + 0];
        float dy = pos[r * 3 + 1] - pos[c * 3 + 1];
        float dz = pos[r * 3 + 2] - pos[c * 3 + 2];
        float ew = sqrtf(dx * dx + dy * dy + dz * dz);
        g_ew[e] = ew;
        g_Cc[e] = 0.5f * (cosf(ew * (PI_F / CUTF)) + 1.f);
    }
}

// ---------------- edge filter MLP + gather-mul + scatter-add ----------------
// warp per edge; w1 [50,128], w2 [128,128] staged in dynamic smem.
__global__ void edge_kernel(const int* __restrict__ ei, const float* __restrict__ eattr,
                            const float* __restrict__ w1, const float* __restrict__ b1,
                            const float* __restrict__ w2, const float* __restrict__ b2) {
    extern __shared__ float sm[];
    float* w1s = sm;                 // 50*128
    float* b1s = w1s + NF * HID;     // 128
    float* w2s = b1s + HID;          // 128*128
    float* b2s = w2s + HID * HID;    // 128
    float* eas = b2s + HID;          // 8 * 52
    float* t1s = eas + 8 * 52;       // 8 * 128

    for (int i = threadIdx.x; i < NF * HID; i += blockDim.x) w1s[i] = w1[i];
    for (int i = threadIdx.x; i < HID * HID; i += blockDim.x) w2s[i] = w2[i];
    if (threadIdx.x < HID) { b1s[threadIdx.x] = b1[threadIdx.x]; b2s[threadIdx.x] = b2[threadIdx.x]; }
    __syncthreads();

    const int wid = threadIdx.x >> 5;
    const int lane = threadIdx.x & 31;
    float* ea = eas + wid * 52;
    float* t1 = t1s + wid * HID;
    const int gw = blockIdx.x * 8 + wid;
    const int nw = gridDim.x * 8;
    const float step = CUTF / (float)(NGS - 1);
    const float coeff = -0.5f / (step * step);
    const int c0 = lane * 4;

    for (int e = gw; e < N_EDGES; e += nw) {
        int row = ei[e], col = ei[N_EDGES + e];
        float ew = g_ew[e];
        if (lane < NB) ea[lane] = eattr[e * NB + lane];
        #pragma unroll
        for (int k = lane; k < NGS; k += 32) {
            float d = ew - (float)k * step;
            ea[NB + k] = __expf(coeff * d * d);
        }
        __syncwarp();

        // hidden = ssp(ea @ w1 + b1)
        float4 bv1 = *(const float4*)(b1s + c0);
        float a0 = bv1.x, a1 = bv1.y, a2 = bv1.z, a3 = bv1.w;
        #pragma unroll 10
        for (int k = 0; k < NF; k++) {
            float v = ea[k];
            float4 w = *(const float4*)(w1s + k * HID + c0);
            a0 += v * w.x; a1 += v * w.y; a2 += v * w.z; a3 += v * w.w;
        }
        float4 tv;
        tv.x = sspf(a0); tv.y = sspf(a1); tv.z = sspf(a2); tv.w = sspf(a3);
        *(float4*)(t1 + c0) = tv;
        __syncwarp();

        // W = (hidden @ w2 + b2) * C
        float4 bv2 = *(const float4*)(b2s + c0);
        float o0 = bv2.x, o1 = bv2.y, o2 = bv2.z, o3 = bv2.w;
        #pragma unroll 8
        for (int k = 0; k < HID; k++) {
            float v = t1[k];
            float4 w = *(const float4*)(w2s + k * HID + c0);
            o0 += v * w.x; o1 += v * w.y; o2 += v * w.z; o3 += v * w.w;
        }
        float Cw = g_Cc[e];
        float4 xv = *(const float4*)(g_xh + (size_t)row * HID + c0);
        float* ag = g_agg + (size_t)col * HID + c0;
        atomicAdd(ag + 0, xv.x * o0 * Cw);
        atomicAdd(ag + 1, xv.y * o1 * Cw);
        atomicAdd(ag + 2, xv.z * o2 * Cw);
        atomicAdd(ag + 3, xv.w * o3 * Cw);
        __syncwarp();
    }
}

// ---------------- node GEMM [N,128] @ [128,128] ----------------
// MODE 0: Y = X@W (+b); MODE 1: Y = ssp(X@W + b); MODE 2: Y += X@W + b
template <int MODE>
__global__ void node_gemm(const float* __restrict__ X, const float* __restrict__ W,
                          const float* __restrict__ bias, float* __restrict__ Y) {
    extern __shared__ float sm[];
    float* Ws = sm;                   // 128*128
    float* bs = Ws + HID * HID;       // 128
    float* xs = bs + HID;             // 8*128
    for (int i = threadIdx.x; i < HID * HID; i += blockDim.x) Ws[i] = W[i];
    if (threadIdx.x < HID) bs[threadIdx.x] = bias ? bias[threadIdx.x] : 0.f;
    __syncthreads();

    const int wid = threadIdx.x >> 5;
    const int lane = threadIdx.x & 31;
    float* xw = xs + wid * HID;
    const int gw = blockIdx.x * 8 + wid;
    const int nw = gridDim.x * 8;
    const int c0 = lane * 4;

    for (int n = gw; n < N_NODES; n += nw) {
        *(float4*)(xw + c0) = *(const float4*)(X + (size_t)n * HID + c0);
        __syncwarp();
        float4 bv = *(const float4*)(bs + c0);
        float a0 = bv.x, a1 = bv.y, a2 = bv.z, a3 = bv.w;
        #pragma unroll 8
        for (int k = 0; k < HID; k++) {
            float v = xw[k];
            float4 w = *(const float4*)(Ws + k * HID + c0);
            a0 += v * w.x; a1 += v * w.y; a2 += v * w.z; a3 += v * w.w;
        }
        float4 r;
        if (MODE == 1) { r.x = sspf(a0); r.y = sspf(a1); r.z = sspf(a2); r.w = sspf(a3); }
        else           { r.x = a0; r.y = a1; r.z = a2; r.w = a3; }
        float* yp = Y + (size_t)n * HID + c0;
        if (MODE == 2) {
            float4 old = *(const float4*)yp;
            r.x += old.x; r.y += old.y; r.z += old.z; r.w += old.w;
        }
        *(float4*)yp = r;
        __syncwarp();
    }
}

// ---------------- readout: ssp(h@o1+b)@o2 + b2, segment-sum over batch ----------------
__global__ void readout_kernel(const int* __restrict__ batch,
                               const float* __restrict__ o1w, const float* __restrict__ o1b,
                               const float* __restrict__ o2w, const float* __restrict__ o2b,
                               float* __restrict__ out) {
    __shared__ float o1s[HID * 64];
    __shared__ float o2s[64];
    __shared__ float xs[8][HID];
    for (int i = threadIdx.x; i < HID * 64; i += blockDim.x) o1s[i] = o1w[i];
    if (threadIdx.x < 64) o2s[threadIdx.x] = o2w[threadIdx.x];
    __syncthreads();

    const int wid = threadIdx.x >> 5;
    const int lane = threadIdx.x & 31;
    const int gw = blockIdx.x * 8 + wid;
    const int nw = gridDim.x * 8;
    const float b0 = o1b[lane], b1v = o1b[lane + 32];
    const float w20 = o2s[lane], w21 = o2s[lane + 32];
    const float ob = o2b[0];

    for (int n = gw; n < N_NODES; n += nw) {
        *(float4*)(&xs[wid][lane * 4]) = *(const float4*)(g_h + (size_t)n * HID + lane * 4);
        __syncwarp();
        float t0 = b0, t1 = b1v;
        #pragma unroll 8
        for (int k = 0; k < HID; k++) {
            float v = xs[wid][k];
            t0 += v * o1s[k * 64 + lane];
            t1 += v * o1s[k * 64 + lane + 32];
        }
        float p = sspf(t0) * w20 + sspf(t1) * w21;
        #pragma unroll
        for (int off = 16; off; off >>= 1) p += __shfl_down_sync(0xffffffffu, p, off);
        if (lane == 0) atomicAdd(&out[batch[n]], p + ob);
        __syncwarp();
    }
}

// ---------------- launch ----------------
extern "C" void kernel_launch(void* const* d_in, const int* in_sizes, int n_in,
                              void* d_out, int out_size) {
    const int*   z      = (const int*)  d_in[0];
    const float* pos    = (const float*)d_in[1];
    const int*   batch  = (const int*)  d_in[2];
    const int*   ei     = (const int*)  d_in[3];
    const float* eattr  = (const float*)d_in[4];
    const float* emb    = (const float*)d_in[5];
    const float* mlp_w1 = (const float*)d_in[6];
    const float* mlp_b1 = (const float*)d_in[7];
    const float* mlp_w2 = (const float*)d_in[8];
    const float* mlp_b2 = (const float*)d_in[9];
    const float* cf1_w  = (const float*)d_in[10];
    const float* cf2_w  = (const float*)d_in[11];
    const float* cf2_b  = (const float*)d_in[12];
    const float* lin_w  = (const float*)d_in[13];
    const float* lin_b  = (const float*)d_in[14];
    const float* o1w    = (const float*)d_in[15];
    const float* o1b    = (const float*)d_in[16];
    const float* o2w    = (const float*)d_in[17];
    const float* o2b    = (const float*)d_in[18];
    float* out = (float*)d_out;

    const int EDGE_SMEM = (NF * HID + HID + HID * HID + HID + 8 * 52 + 8 * HID) * (int)sizeof(float);
    const int GEMM_SMEM = (HID * HID + HID + 8 * HID) * (int)sizeof(float);
    cudaFuncSetAttribute(edge_kernel,  cudaFuncAttributeMaxDynamicSharedMemorySize, EDGE_SMEM);
    cudaFuncSetAttribute(node_gemm<0>, cudaFuncAttributeMaxDynamicSharedMemorySize, GEMM_SMEM);
    cudaFuncSetAttribute(node_gemm<1>, cudaFuncAttributeMaxDynamicSharedMemorySize, GEMM_SMEM);
    cudaFuncSetAttribute(node_gemm<2>, cudaFuncAttributeMaxDynamicSharedMemorySize, GEMM_SMEM);

    float *ph, *pxh, *pagg, *ptmp;
    cudaGetSymbolAddress((void**)&ph,   g_h);
    cudaGetSymbolAddress((void**)&pxh,  g_xh);
    cudaGetSymbolAddress((void**)&pagg, g_agg);
    cudaGetSymbolAddress((void**)&ptmp, g_tmp);

    zero_out_kernel<<<1, 32>>>(out);
    embed_kernel<<<(N_NODES * HID + 255) / 256, 256>>>(z, emb);
    edge_pre_kernel<<<(N_EDGES + 255) / 256, 256>>>(ei, pos);

    for (int l = 0; l < 3; l++) {
        node_gemm<0><<<444, 256, GEMM_SMEM>>>(ph, cf1_w + (size_t)l * HID * HID, nullptr, pxh);
        zero_agg_kernel<<<(N_NODES * HID + 255) / 256, 256>>>();
        edge_kernel<<<296, 256, EDGE_SMEM>>>(ei, eattr,
                                             mlp_w1 + (size_t)l * NF * HID, mlp_b1 + (size_t)l * HID,
                                             mlp_w2 + (size_t)l * HID * HID, mlp_b2 + (size_t)l * HID);
        node_gemm<1><<<444, 256, GEMM_SMEM>>>(pagg, cf2_w + (size_t)l * HID * HID, cf2_b + (size_t)l * HID, ptmp);
        node_gemm<2><<<444, 256, GEMM_SMEM>>>(ptmp, lin_w + (size_t)l * HID * HID, lin_b + (size_t)l * HID, ph);
    }
    readout_kernel<<<592, 256>>>(batch, o1w, o1b, o2w, o2b, out);
}

// round 3
// speedup vs baseline: 3.7971x; 3.7971x over previous
#include <cuda_runtime.h>
#include <cstdint>
#include <math.h>

#define N_NODES 20000
#define N_EDGES 640000
#define HID 128
#define NB 3
#define NGS 47
#define NF 50
#define KP1 56            // K for GEMM1 (50 padded to 56, 7 k-steps of 8)
#define B_GRAPHS 16
#define LOG2F_ 0.69314718055994530942f
#define CUTF 10.0f
#define PI_F 3.14159265358979323846f
#define EDGE_TILES (N_EDGES / 128)   // 5000

#define W1_STRIDE 60      // padded K stride for WT1 / A tile
#define W2_STRIDE 132     // padded K stride for WT2 / H tile

// smem float offsets
#define OFF_W1 0                       // [128][60]  = 7680
#define OFF_W2 7680                    // [128][132] = 16896
#define OFF_U  24576                   // union: A [128][60] / H [128][132] = 16896
#define OFF_B1 41472                   // [128]
#define OFF_B2 41600                   // [128]
#define EK_FLOATS 41728
#define EK_SMEM (EK_FLOATS * 4)

// ---------------- scratch ----------------
__device__ float g_h  [N_NODES * HID];
__device__ float g_xh [N_NODES * HID];
__device__ float g_agg[N_NODES * HID];
__device__ float g_tmp[N_NODES * HID];
__device__ float g_ew [N_EDGES];
__device__ float g_Cc [N_EDGES];

__device__ __forceinline__ float sspf(float x) {
    float sp = (x > 15.f) ? x : log1pf(__expf(x));
    return sp - LOG2F_;
}
__device__ __forceinline__ uint32_t f2tf(float v) {
    uint32_t o; asm("cvt.rna.tf32.f32 %0, %1;" : "=r"(o) : "f"(v)); return o;
}
__device__ __forceinline__ void mma_tf32(float& c0, float& c1, float& c2, float& c3,
                                         uint32_t a0, uint32_t a1, uint32_t a2, uint32_t a3,
                                         uint32_t b0, uint32_t b1) {
    asm volatile("mma.sync.aligned.m16n8k8.row.col.f32.tf32.tf32.f32 "
                 "{%0,%1,%2,%3}, {%4,%5,%6,%7}, {%8,%9}, {%0,%1,%2,%3};"
                 : "+f"(c0), "+f"(c1), "+f"(c2), "+f"(c3)
                 : "r"(a0), "r"(a1), "r"(a2), "r"(a3), "r"(b0), "r"(b1));
}

// ---------------- small kernels ----------------
__global__ void zero_out_kernel(float* out) {
    if (threadIdx.x < B_GRAPHS) out[threadIdx.x] = 0.f;
}
__global__ void embed_kernel(const int* __restrict__ z, const float* __restrict__ emb) {
    int i = blockIdx.x * blockDim.x + threadIdx.x;
    if (i < N_NODES * HID) {
        int n = i >> 7, c = i & 127;
        g_h[i] = emb[z[n] * HID + c];
    }
}
__global__ void zero_agg_kernel() {
    int i = blockIdx.x * blockDim.x + threadIdx.x;
    if (i < N_NODES * HID) g_agg[i] = 0.f;
}
__global__ void edge_pre_kernel(const int* __restrict__ ei, const float* __restrict__ pos) {
    int e = blockIdx.x * blockDim.x + threadIdx.x;
    if (e < N_EDGES) {
        int r = ei[e], c = ei[N_EDGES + e];
        float dx = pos[r * 3 + 0] - pos[c * 3 + 0];
        float dy = pos[r * 3 + 1] - pos[c * 3 + 1];
        float dz = pos[r * 3 + 2] - pos[c * 3 + 2];
        float ew = sqrtf(dx * dx + dy * dy + dz * dz);
        g_ew[e] = ew;
        g_Cc[e] = 0.5f * (cosf(ew * (PI_F / CUTF)) + 1.f);
    }
}

// ---------------- edge filter MLP via mma.sync tf32 ----------------
// 512 threads = 16 warps. warp w: row-tile rt = w&7 (rows 16rt..16rt+15),
// n-half nh = w>>3 (cols nh*64 .. +63, 8 n-tiles of 8).
__global__ void __launch_bounds__(512, 1)
edge_mma_kernel(const int* __restrict__ ei, const float* __restrict__ eattr,
                const float* __restrict__ w1, const float* __restrict__ b1,
                const float* __restrict__ w2, const float* __restrict__ b2) {
    extern __shared__ float sm[];
    float* w1s = sm + OFF_W1;
    float* w2s = sm + OFF_W2;
    float* us  = sm + OFF_U;
    float* b1s = sm + OFF_B1;
    float* b2s = sm + OFF_B2;

    const int tid = threadIdx.x;
    const int wid = tid >> 5, lane = tid & 31;
    const int g = lane >> 2, tg = lane & 3;   // groupID / thread-in-group
    const int rt = wid & 7, nh = wid >> 3;

    // ---- stage weights (transposed, tf32-converted) ----
    for (int i = tid; i < 128 * KP1; i += 512) {
        int n = i / KP1, k = i - n * KP1;
        float v = (k < NF) ? w1[k * HID + n] : 0.f;
        w1s[n * W1_STRIDE + k] = __uint_as_float(f2tf(v));
    }
    for (int i = tid; i < 128 * 128; i += 512) {
        int n = i >> 7, k = i & 127;
        w2s[n * W2_STRIDE + k] = __uint_as_float(f2tf(w2[k * HID + n]));
    }
    if (tid < HID) { b1s[tid] = b1[tid]; b2s[tid] = b2[tid]; }
    __syncthreads();

    const float step = CUTF / (float)(NGS - 1);
    const float coeff = -0.5f / (step * step);
    const int eloc = tid >> 2;          // feature phase: edge in tile
    const int fsub = tid & 3;           // 14 feature cols each

    for (int t = blockIdx.x; t < EDGE_TILES; t += gridDim.x) {
        const int e0 = t * 128;
        // ---- feature tile A [128][KP1] (tf32) ----
        {
            int e = e0 + eloc;
            float ew = g_ew[e];
            float* arow = us + eloc * W1_STRIDE;
            #pragma unroll
            for (int j = 0; j < 14; j++) {
                int k = fsub * 14 + j;
                float v;
                if (k < NB) v = eattr[e * NB + k];
                else if (k < NF) {
                    float d = ew - (float)(k - NB) * step;
                    v = __expf(coeff * d * d);
                } else v = 0.f;
                arow[k] = __uint_as_float(f2tf(v));
            }
        }
        __syncthreads();

        // ---- GEMM1: D = A @ W1 (K=56), acc[8 n-tiles][4] ----
        float acc[8][4];
        #pragma unroll
        for (int j = 0; j < 8; j++) { acc[j][0] = acc[j][1] = acc[j][2] = acc[j][3] = 0.f; }
        {
            const float* A = us;
            #pragma unroll
            for (int ks = 0; ks < 7; ks++) {
                int k0 = ks * 8;
                uint32_t a0 = __float_as_uint(A[(rt * 16 + g) * W1_STRIDE + k0 + tg]);
                uint32_t a1 = __float_as_uint(A[(rt * 16 + g + 8) * W1_STRIDE + k0 + tg]);
                uint32_t a2 = __float_as_uint(A[(rt * 16 + g) * W1_STRIDE + k0 + tg + 4]);
                uint32_t a3 = __float_as_uint(A[(rt * 16 + g + 8) * W1_STRIDE + k0 + tg + 4]);
                #pragma unroll
                for (int j = 0; j < 8; j++) {
                    int n0 = nh * 64 + j * 8;
                    uint32_t b0 = __float_as_uint(w1s[(n0 + g) * W1_STRIDE + k0 + tg]);
                    uint32_t bb1 = __float_as_uint(w1s[(n0 + g) * W1_STRIDE + k0 + tg + 4]);
                    mma_tf32(acc[j][0], acc[j][1], acc[j][2], acc[j][3], a0, a1, a2, a3, b0, bb1);
                }
            }
        }
        __syncthreads();   // all warps done reading A before H overwrites union

        // ---- epilogue1: H = tf32(ssp(D + b1)) into union [128][132] ----
        {
            int r0 = rt * 16 + g, r1 = r0 + 8;
            #pragma unroll
            for (int j = 0; j < 8; j++) {
                int c = nh * 64 + j * 8 + tg * 2;
                float bx = b1s[c], by = b1s[c + 1];
                float2 v0 = make_float2(__uint_as_float(f2tf(sspf(acc[j][0] + bx))),
                                        __uint_as_float(f2tf(sspf(acc[j][1] + by))));
                float2 v1 = make_float2(__uint_as_float(f2tf(sspf(acc[j][2] + bx))),
                                        __uint_as_float(f2tf(sspf(acc[j][3] + by))));
                *(float2*)(us + r0 * W2_STRIDE + c) = v0;
                *(float2*)(us + r1 * W2_STRIDE + c) = v1;
            }
        }
        __syncthreads();

        // ---- GEMM2: D = H @ W2 (K=128) ----
        #pragma unroll
        for (int j = 0; j < 8; j++) { acc[j][0] = acc[j][1] = acc[j][2] = acc[j][3] = 0.f; }
        {
            const float* A = us;
            #pragma unroll
            for (int ks = 0; ks < 16; ks++) {
                int k0 = ks * 8;
                uint32_t a0 = __float_as_uint(A[(rt * 16 + g) * W2_STRIDE + k0 + tg]);
                uint32_t a1 = __float_as_uint(A[(rt * 16 + g + 8) * W2_STRIDE + k0 + tg]);
                uint32_t a2 = __float_as_uint(A[(rt * 16 + g) * W2_STRIDE + k0 + tg + 4]);
                uint32_t a3 = __float_as_uint(A[(rt * 16 + g + 8) * W2_STRIDE + k0 + tg + 4]);
                #pragma unroll
                for (int j = 0; j < 8; j++) {
                    int n0 = nh * 64 + j * 8;
                    uint32_t b0 = __float_as_uint(w2s[(n0 + g) * W2_STRIDE + k0 + tg]);
                    uint32_t bb1 = __float_as_uint(w2s[(n0 + g) * W2_STRIDE + k0 + tg + 4]);
                    mma_tf32(acc[j][0], acc[j][1], acc[j][2], acc[j][3], a0, a1, a2, a3, b0, bb1);
                }
            }
        }

        // ---- epilogue2: W=(D+b2)*C; msg=xh[row]*W; red -> agg[col] ----
        {
            int m0 = rt * 16 + g;
            int ea = e0 + m0, eb = ea + 8;
            int rowA = ei[ea], colA = ei[N_EDGES + ea];
            int rowB = ei[eb], colB = ei[N_EDGES + eb];
            float Ca = g_Cc[ea], Cb = g_Cc[eb];
            const float* xA = g_xh + (size_t)rowA * HID;
            const float* xB = g_xh + (size_t)rowB * HID;
            float* aA = g_agg + (size_t)colA * HID;
            float* aB = g_agg + (size_t)colB * HID;
            #pragma unroll
            for (int j = 0; j < 8; j++) {
                int c = nh * 64 + j * 8 + tg * 2;
                float bx = b2s[c], by = b2s[c + 1];
                float2 xv = *(const float2*)(xA + c);
                float p0 = (acc[j][0] + bx) * Ca * xv.x;
                float p1 = (acc[j][1] + by) * Ca * xv.y;
                asm volatile("red.global.add.v2.f32 [%0], {%1, %2};"
                             :: "l"(aA + c), "f"(p0), "f"(p1) : "memory");
                float2 xw = *(const float2*)(xB + c);
                float q0 = (acc[j][2] + bx) * Cb * xw.x;
                float q1 = (acc[j][3] + by) * Cb * xw.y;
                asm volatile("red.global.add.v2.f32 [%0], {%1, %2};"
                             :: "l"(aB + c), "f"(q0), "f"(q1) : "memory");
            }
        }
        __syncthreads();   // protect union before next tile's feature writes
    }
}

// ---------------- node GEMM: 4 nodes per warp, persistent ----------------
template <int MODE>  // 0: Y=XW; 1: Y=ssp(XW+b); 2: Y+=XW+b
__global__ void node_gemm(const float* __restrict__ X, const float* __restrict__ W,
                          const float* __restrict__ bias, float* __restrict__ Y) {
    extern __shared__ float sm[];
    float* Ws = sm;                    // 128*128
    float* bs = Ws + HID * HID;        // 128
    float* xs = bs + HID;              // 8 warps * 512
    for (int i = threadIdx.x; i < HID * HID; i += blockDim.x) Ws[i] = W[i];
    if (threadIdx.x < HID) bs[threadIdx.x] = bias ? bias[threadIdx.x] : 0.f;
    __syncthreads();

    const int wid = threadIdx.x >> 5, lane = threadIdx.x & 31;
    float* xw = xs + wid * 512;
    const int gw = blockIdx.x * 8 + wid, nw = gridDim.x * 8;
    const int c0 = lane * 4;

    for (int gidx = gw; gidx < N_NODES / 4; gidx += nw) {
        int n0 = gidx * 4;
        #pragma unroll
        for (int j = 0; j < 4; j++) {
            int f = lane + 32 * j;
            ((float4*)xw)[f] = ((const float4*)(X + (size_t)n0 * HID))[f];
        }
        __syncwarp();
        float4 bv = *(const float4*)(bs + c0);
        float a[4][4];
        #pragma unroll
        for (int r = 0; r < 4; r++) { a[r][0] = bv.x; a[r][1] = bv.y; a[r][2] = bv.z; a[r][3] = bv.w; }
        #pragma unroll 4
        for (int k = 0; k < HID; k++) {
            float4 w = *(const float4*)(Ws + k * HID + c0);
            #pragma unroll
            for (int r = 0; r < 4; r++) {
                float v = xw[r * HID + k];
                a[r][0] += v * w.x; a[r][1] += v * w.y; a[r][2] += v * w.z; a[r][3] += v * w.w;
            }
        }
        #pragma unroll
        for (int r = 0; r < 4; r++) {
            float4 rr;
            if (MODE == 1) { rr.x = sspf(a[r][0]); rr.y = sspf(a[r][1]); rr.z = sspf(a[r][2]); rr.w = sspf(a[r][3]); }
            else           { rr.x = a[r][0]; rr.y = a[r][1]; rr.z = a[r][2]; rr.w = a[r][3]; }
            float* yp = Y + (size_t)(n0 + r) * HID + c0;
            if (MODE == 2) {
                float4 old = *(const float4*)yp;
                rr.x += old.x; rr.y += old.y; rr.z += old.z; rr.w += old.w;
            }
            *(float4*)yp = rr;
        }
        __syncwarp();
    }
}

// ---------------- readout ----------------
__global__ void readout_kernel(const int* __restrict__ batch,
                               const float* __restrict__ o1w, const float* __restrict__ o1b,
                               const float* __restrict__ o2w, const float* __restrict__ o2b,
                               float* __restrict__ out) {
    __shared__ float o1s[HID * 64];
    __shared__ float o2s[64];
    __shared__ float xs[8][HID];
    for (int i = threadIdx.x; i < HID * 64; i += blockDim.x) o1s[i] = o1w[i];
    if (threadIdx.x < 64) o2s[threadIdx.x] = o2w[threadIdx.x];
    __syncthreads();

    const int wid = threadIdx.x >> 5, lane = threadIdx.x & 31;
    const int gw = blockIdx.x * 8 + wid, nw = gridDim.x * 8;
    const float b0 = o1b[lane], b1v = o1b[lane + 32];
    const float w20 = o2s[lane], w21 = o2s[lane + 32];
    const float ob = o2b[0];

    for (int n = gw; n < N_NODES; n += nw) {
        *(float4*)(&xs[wid][lane * 4]) = *(const float4*)(g_h + (size_t)n * HID + lane * 4);
        __syncwarp();
        float t0 = b0, t1 = b1v;
        #pragma unroll 8
        for (int k = 0; k < HID; k++) {
            float v = xs[wid][k];
            t0 += v * o1s[k * 64 + lane];
            t1 += v * o1s[k * 64 + lane + 32];
        }
        float p = sspf(t0) * w20 + sspf(t1) * w21;
        #pragma unroll
        for (int off = 16; off; off >>= 1) p += __shfl_down_sync(0xffffffffu, p, off);
        if (lane == 0) atomicAdd(&out[batch[n]], p + ob);
        __syncwarp();
    }
}

// ---------------- launch ----------------
extern "C" void kernel_launch(void* const* d_in, const int* in_sizes, int n_in,
                              void* d_out, int out_size) {
    const int*   z      = (const int*)  d_in[0];
    const float* pos    = (const float*)d_in[1];
    const int*   batch  = (const int*)  d_in[2];
    const int*   ei     = (const int*)  d_in[3];
    const float* eattr  = (const float*)d_in[4];
    const float* emb    = (const float*)d_in[5];
    const float* mlp_w1 = (const float*)d_in[6];
    const float* mlp_b1 = (const float*)d_in[7];
    const float* mlp_w2 = (const float*)d_in[8];
    const float* mlp_b2 = (const float*)d_in[9];
    const float* cf1_w  = (const float*)d_in[10];
    const float* cf2_w  = (const float*)d_in[11];
    const float* cf2_b  = (const float*)d_in[12];
    const float* lin_w  = (const float*)d_in[13];
    const float* lin_b  = (const float*)d_in[14];
    const float* o1w    = (const float*)d_in[15];
    const float* o1b    = (const float*)d_in[16];
    const float* o2w    = (const float*)d_in[17];
    const float* o2b    = (const float*)d_in[18];
    float* out = (float*)d_out;

    const int GEMM_SMEM = (HID * HID + HID + 8 * 512) * (int)sizeof(float);
    cudaFuncSetAttribute(edge_mma_kernel, cudaFuncAttributeMaxDynamicSharedMemorySize, EK_SMEM);
    cudaFuncSetAttribute(node_gemm<0>, cudaFuncAttributeMaxDynamicSharedMemorySize, GEMM_SMEM);
    cudaFuncSetAttribute(node_gemm<1>, cudaFuncAttributeMaxDynamicSharedMemorySize, GEMM_SMEM);
    cudaFuncSetAttribute(node_gemm<2>, cudaFuncAttributeMaxDynamicSharedMemorySize, GEMM_SMEM);

    float *ph, *pxh, *pagg, *ptmp;
    cudaGetSymbolAddress((void**)&ph,   g_h);
    cudaGetSymbolAddress((void**)&pxh,  g_xh);
    cudaGetSymbolAddress((void**)&pagg, g_agg);
    cudaGetSymbolAddress((void**)&ptmp, g_tmp);

    zero_out_kernel<<<1, 32>>>(out);
    embed_kernel<<<(N_NODES * HID + 255) / 256, 256>>>(z, emb);
    edge_pre_kernel<<<(N_EDGES + 255) / 256, 256>>>(ei, pos);

    for (int l = 0; l < 3; l++) {
        node_gemm<0><<<296, 256, GEMM_SMEM>>>(ph, cf1_w + (size_t)l * HID * HID, nullptr, pxh);
        zero_agg_kernel<<<(N_NODES * HID + 255) / 256, 256>>>();
        edge_mma_kernel<<<148, 512, EK_SMEM>>>(ei, eattr,
                                               mlp_w1 + (size_t)l * NF * HID, mlp_b1 + (size_t)l * HID,
                                               mlp_w2 + (size_t)l * HID * HID, mlp_b2 + (size_t)l * HID);
        node_gemm<1><<<296, 256, GEMM_SMEM>>>(pagg, cf2_w + (size_t)l * HID * HID, cf2_b + (size_t)l * HID, ptmp);
        node_gemm<2><<<296, 256, GEMM_SMEM>>>(ptmp, lin_w + (size_t)l * HID * HID, lin_b + (size_t)l * HID, ph);
    }
    readout_kernel<<<592, 256>>>(batch, o1w, o1b, o2w, o2b, out);
}

// round 4
// speedup vs baseline: 4.7811x; 1.2591x over previous
#include <cuda_runtime.h>
#include <cuda_fp16.h>
#include <cstdint>
#include <math.h>

#define N_NODES 20000
#define N_EDGES 640000
#define HID 128
#define NB 3
#define NGS 47
#define NF 50
#define B_GRAPHS 16
#define LOG2F_ 0.69314718055994530942f
#define CUTF 10.0f
#define PI_F 3.14159265358979323846f
#define EDGE_TILES (N_EDGES / 128)   // 5000

#define SA1 72     // halves stride for A / W1 tiles (K=64 + 8 pad) -> 144B rows
#define SA2 136    // halves stride for H / W2 tiles (K=128 + 8 pad) -> 272B rows

// smem byte offsets (all 16B aligned)
#define OFF_W1h 0                         // 128*72*2  = 18432
#define OFF_W2h 18432                     // 128*136*2 = 34816
#define OFF_A   53248                     // 128*72*2  = 18432
#define OFF_H   71680                     // 128*136*2 = 34816
#define OFF_B1  106496                    // 512
#define OFF_B2  107008                    // 512
#define EK_SMEM 107520                    // ~105KB -> 2 CTAs/SM

// ---------------- scratch ----------------
__device__ float g_h  [N_NODES * HID];
__device__ float g_xh [N_NODES * HID];
__device__ float g_agg[N_NODES * HID];
__device__ float g_tmp[N_NODES * HID];
__device__ float g_ew [N_EDGES];
__device__ float g_Cc [N_EDGES];

__device__ __forceinline__ float sspf(float x) {
    float sp = (x > 15.f) ? x : log1pf(__expf(x));
    return sp - LOG2F_;
}
__device__ __forceinline__ uint32_t smem_to_u32(const void* p) {
    uint32_t a;
    asm("{ .reg .u64 t; cvta.to.shared.u64 t, %1; cvt.u32.u64 %0, t; }" : "=r"(a) : "l"(p));
    return a;
}
__device__ __forceinline__ void ldm_x4(uint32_t& r0, uint32_t& r1, uint32_t& r2, uint32_t& r3, uint32_t a) {
    asm volatile("ldmatrix.sync.aligned.m8n8.x4.shared.b16 {%0,%1,%2,%3}, [%4];"
                 : "=r"(r0), "=r"(r1), "=r"(r2), "=r"(r3) : "r"(a));
}
__device__ __forceinline__ void mma16816(float* c, uint32_t a0, uint32_t a1, uint32_t a2, uint32_t a3,
                                         uint32_t b0, uint32_t b1) {
    asm volatile("mma.sync.aligned.m16n8k16.row.col.f32.f16.f16.f32 "
                 "{%0,%1,%2,%3}, {%4,%5,%6,%7}, {%8,%9}, {%0,%1,%2,%3};"
                 : "+f"(c[0]), "+f"(c[1]), "+f"(c[2]), "+f"(c[3])
                 : "r"(a0), "r"(a1), "r"(a2), "r"(a3), "r"(b0), "r"(b1));
}

// ---------------- small kernels ----------------
__global__ void zero_out_kernel(float* out) {
    if (threadIdx.x < B_GRAPHS) out[threadIdx.x] = 0.f;
}
__global__ void embed_kernel(const int* __restrict__ z, const float* __restrict__ emb) {
    int i = blockIdx.x * blockDim.x + threadIdx.x;
    if (i < N_NODES * HID) {
        int n = i >> 7, c = i & 127;
        g_h[i] = emb[z[n] * HID + c];
    }
}
__global__ void edge_pre_kernel(const int* __restrict__ ei, const float* __restrict__ pos) {
    int e = blockIdx.x * blockDim.x + threadIdx.x;
    if (e < N_EDGES) {
        int r = ei[e], c = ei[N_EDGES + e];
        float dx = pos[r * 3 + 0] - pos[c * 3 + 0];
        float dy = pos[r * 3 + 1] - pos[c * 3 + 1];
        float dz = pos[r * 3 + 2] - pos[c * 3 + 2];
        float ew = sqrtf(dx * dx + dy * dy + dz * dz);
        g_ew[e] = ew;
        g_Cc[e] = 0.5f * (cosf(ew * (PI_F / CUTF)) + 1.f);
    }
}

// ---------------- edge filter MLP: fp16 mma + ldmatrix, 2 CTAs/SM ----------------
__device__ __forceinline__ void featgen(half* Ah, const float* eattr, int e0, int tid,
                                        float step, float coeff) {
    int e = e0 + (tid >> 1);
    int seg = tid & 1;
    float ew = g_ew[e];
    half2* arow = (half2*)(Ah + (size_t)(tid >> 1) * SA1 + seg * 32);
    float f[32];
    if (seg == 0) {
        f[0] = eattr[e * NB + 0];
        f[1] = eattr[e * NB + 1];
        f[2] = eattr[e * NB + 2];
        #pragma unroll
        for (int j = 3; j < 32; j++) {
            float d = ew - (float)(j - 3) * step;
            f[j] = __expf(coeff * d * d);
        }
    } else {
        #pragma unroll
        for (int j = 0; j < 18; j++) {
            float d = ew - (float)(29 + j) * step;
            f[j] = __expf(coeff * d * d);
        }
        #pragma unroll
        for (int j = 18; j < 32; j++) f[j] = 0.f;
    }
    #pragma unroll
    for (int j = 0; j < 16; j++) arow[j] = __floats2half2_rn(f[2 * j], f[2 * j + 1]);
}

__global__ void __launch_bounds__(256, 2)
edge_mma_kernel(const int* __restrict__ ei, const float* __restrict__ eattr,
                const float* __restrict__ w1, const float* __restrict__ b1,
                const float* __restrict__ w2, const float* __restrict__ b2) {
    extern __shared__ char smem[];
    half* w1h = (half*)(smem + OFF_W1h);
    half* w2h = (half*)(smem + OFF_W2h);
    half* Ah  = (half*)(smem + OFF_A);
    half* Hh  = (half*)(smem + OFF_H);
    float* b1s = (float*)(smem + OFF_B1);
    float* b2s = (float*)(smem + OFF_B2);

    const int tid = threadIdx.x, wid = tid >> 5, lane = tid & 31;
    const int g = lane >> 2, tg = lane & 3;
    const int rt = wid & 3, nh = wid >> 2;     // rows rt*32..+31, cols nh*64..+63

    // stage weights transposed -> fp16
    for (int i = tid; i < 128 * 64; i += 256) {
        int n = i >> 6, k = i & 63;
        w1h[n * SA1 + k] = __float2half_rn((k < NF) ? w1[k * HID + n] : 0.f);
    }
    for (int i = tid; i < 128 * 128; i += 256) {
        int n = i >> 7, k = i & 127;
        w2h[n * SA2 + k] = __float2half_rn(w2[k * HID + n]);
    }
    if (tid < HID) { b1s[tid] = b1[tid]; b2s[tid] = b2[tid]; }

    const uint32_t aU  = smem_to_u32(Ah);
    const uint32_t hU  = smem_to_u32(Hh);
    const uint32_t w1U = smem_to_u32(w1h);
    const uint32_t w2U = smem_to_u32(w2h);

    const float step = CUTF / (float)(NGS - 1);
    const float coeff = -0.5f / (step * step);

    // ldmatrix lane geometry (shared by A and B tiles)
    const int lrow = lane & 15;                // row within 16-row group
    const int lkh  = (lane >> 4) << 3;         // +8 halves for upper k matrices

    featgen(Ah, eattr, blockIdx.x * 128, tid, step, coeff);
    __syncthreads();

    for (int t = blockIdx.x; t < EDGE_TILES; t += gridDim.x) {
        const int e0 = t * 128;
        float acc[2][8][4];
        #pragma unroll
        for (int mt = 0; mt < 2; mt++)
            #pragma unroll
            for (int j = 0; j < 8; j++)
                #pragma unroll
                for (int q = 0; q < 4; q++) acc[mt][j][q] = 0.f;

        // ---- GEMM1: [128,64]x[64,128], 4 ksteps ----
        #pragma unroll
        for (int ks = 0; ks < 4; ks++) {
            const int k0 = ks * 16;
            uint32_t am[2][4];
            #pragma unroll
            for (int mt = 0; mt < 2; mt++) {
                uint32_t addr = aU + (uint32_t)(((rt * 32 + mt * 16 + lrow) * SA1 + k0 + lkh) << 1);
                ldm_x4(am[mt][0], am[mt][1], am[mt][2], am[mt][3], addr);
            }
            #pragma unroll
            for (int jj = 0; jj < 4; jj++) {
                uint32_t b0, b1r, b2r, b3;
                uint32_t addr = w1U + (uint32_t)(((nh * 64 + jj * 16 + lrow) * SA1 + k0 + lkh) << 1);
                ldm_x4(b0, b1r, b2r, b3, addr);
                #pragma unroll
                for (int mt = 0; mt < 2; mt++) {
                    mma16816(acc[mt][2 * jj],     am[mt][0], am[mt][1], am[mt][2], am[mt][3], b0,  b2r);
                    mma16816(acc[mt][2 * jj + 1], am[mt][0], am[mt][1], am[mt][2], am[mt][3], b1r, b3);
                }
            }
        }
        __syncthreads();   // A consumed (also H from prev iter consumed)

        // ---- epilogue1: H = fp16(ssp(D + b1)) ----
        #pragma unroll
        for (int mt = 0; mt < 2; mt++) {
            int r0 = rt * 32 + mt * 16 + g;
            #pragma unroll
            for (int j = 0; j < 8; j++) {
                int c = nh * 64 + j * 8 + tg * 2;
                float bx = b1s[c], by = b1s[c + 1];
                *(half2*)(Hh + (size_t)r0 * SA2 + c) =
                    __floats2half2_rn(sspf(acc[mt][j][0] + bx), sspf(acc[mt][j][1] + by));
                *(half2*)(Hh + (size_t)(r0 + 8) * SA2 + c) =
                    __floats2half2_rn(sspf(acc[mt][j][2] + bx), sspf(acc[mt][j][3] + by));
            }
        }
        __syncthreads();   // H ready

        // ---- GEMM2: [128,128]x[128,128], 8 ksteps ----
        #pragma unroll
        for (int mt = 0; mt < 2; mt++)
            #pragma unroll
            for (int j = 0; j < 8; j++)
                #pragma unroll
                for (int q = 0; q < 4; q++) acc[mt][j][q] = 0.f;
        #pragma unroll
        for (int ks = 0; ks < 8; ks++) {
            const int k0 = ks * 16;
            uint32_t am[2][4];
            #pragma unroll
            for (int mt = 0; mt < 2; mt++) {
                uint32_t addr = hU + (uint32_t)(((rt * 32 + mt * 16 + lrow) * SA2 + k0 + lkh) << 1);
                ldm_x4(am[mt][0], am[mt][1], am[mt][2], am[mt][3], addr);
            }
            #pragma unroll
            for (int jj = 0; jj < 4; jj++) {
                uint32_t b0, b1r, b2r, b3;
                uint32_t addr = w2U + (uint32_t)(((nh * 64 + jj * 16 + lrow) * SA2 + k0 + lkh) << 1);
                ldm_x4(b0, b1r, b2r, b3, addr);
                #pragma unroll
                for (int mt = 0; mt < 2; mt++) {
                    mma16816(acc[mt][2 * jj],     am[mt][0], am[mt][1], am[mt][2], am[mt][3], b0,  b2r);
                    mma16816(acc[mt][2 * jj + 1], am[mt][0], am[mt][1], am[mt][2], am[mt][3], b1r, b3);
                }
            }
        }

        // feature gen for next tile overlaps epilogue (A is free)
        int tn = t + gridDim.x;
        if (tn < EDGE_TILES) featgen(Ah, eattr, tn * 128, tid, step, coeff);

        // ---- epilogue2: W=(D+b2)*C; msg=xh[row]*W; red -> agg[col] ----
        #pragma unroll
        for (int mt = 0; mt < 2; mt++) {
            int m0 = rt * 32 + mt * 16 + g;
            int ea = e0 + m0, eb = ea + 8;
            int rowA = ei[ea], colA = ei[N_EDGES + ea];
            int rowB = ei[eb], colB = ei[N_EDGES + eb];
            float Ca = g_Cc[ea], Cb = g_Cc[eb];
            const float* xA = g_xh + (size_t)rowA * HID;
            const float* xB = g_xh + (size_t)rowB * HID;
            float* aA = g_agg + (size_t)colA * HID;
            float* aB = g_agg + (size_t)colB * HID;
            #pragma unroll
            for (int j = 0; j < 8; j++) {
                int c = nh * 64 + j * 8 + tg * 2;
                float bx = b2s[c], by = b2s[c + 1];
                float2 xv = *(const float2*)(xA + c);
                float p0 = (acc[mt][j][0] + bx) * Ca * xv.x;
                float p1 = (acc[mt][j][1] + by) * Ca * xv.y;
                asm volatile("red.global.add.v2.f32 [%0], {%1, %2};"
                             :: "l"(aA + c), "f"(p0), "f"(p1) : "memory");
                float2 xw = *(const float2*)(xB + c);
                float q0 = (acc[mt][j][2] + bx) * Cb * xw.x;
                float q1 = (acc[mt][j][3] + by) * Cb * xw.y;
                asm volatile("red.global.add.v2.f32 [%0], {%1, %2};"
                             :: "l"(aB + c), "f"(q0), "f"(q1) : "memory");
            }
        }
        __syncthreads();   // A(t+1) ready; H free
    }
}

// ---------------- node GEMM: 4 nodes per warp, persistent ----------------
// MODE 0: Y=XW, also zeroes g_agg rows; 1: Y=ssp(XW+b); 2: Y+=XW+b
template <int MODE>
__global__ void node_gemm(const float* __restrict__ X, const float* __restrict__ W,
                          const float* __restrict__ bias, float* __restrict__ Y) {
    extern __shared__ float sm[];
    float* Ws = sm;
    float* bs = Ws + HID * HID;
    float* xs = bs + HID;
    for (int i = threadIdx.x; i < HID * HID; i += blockDim.x) Ws[i] = W[i];
    if (threadIdx.x < HID) bs[threadIdx.x] = bias ? bias[threadIdx.x] : 0.f;
    __syncthreads();

    const int wid = threadIdx.x >> 5, lane = threadIdx.x & 31;
    float* xw = xs + wid * 512;
    const int gw = blockIdx.x * 8 + wid, nw = gridDim.x * 8;
    const int c0 = lane * 4;

    for (int gidx = gw; gidx < N_NODES / 4; gidx += nw) {
        int n0 = gidx * 4;
        #pragma unroll
        for (int j = 0; j < 4; j++) {
            int f = lane + 32 * j;
            ((float4*)xw)[f] = ((const float4*)(X + (size_t)n0 * HID))[f];
        }
        __syncwarp();
        float4 bv = *(const float4*)(bs + c0);
        float a[4][4];
        #pragma unroll
        for (int r = 0; r < 4; r++) { a[r][0] = bv.x; a[r][1] = bv.y; a[r][2] = bv.z; a[r][3] = bv.w; }
        #pragma unroll 4
        for (int k = 0; k < HID; k++) {
            float4 w = *(const float4*)(Ws + k * HID + c0);
            #pragma unroll
            for (int r = 0; r < 4; r++) {
                float v = xw[r * HID + k];
                a[r][0] += v * w.x; a[r][1] += v * w.y; a[r][2] += v * w.z; a[r][3] += v * w.w;
            }
        }
        #pragma unroll
        for (int r = 0; r < 4; r++) {
            float4 rr;
            if (MODE == 1) { rr.x = sspf(a[r][0]); rr.y = sspf(a[r][1]); rr.z = sspf(a[r][2]); rr.w = sspf(a[r][3]); }
            else           { rr.x = a[r][0]; rr.y = a[r][1]; rr.z = a[r][2]; rr.w = a[r][3]; }
            float* yp = Y + (size_t)(n0 + r) * HID + c0;
            if (MODE == 2) {
                float4 old = *(const float4*)yp;
                rr.x += old.x; rr.y += old.y; rr.z += old.z; rr.w += old.w;
            }
            *(float4*)yp = rr;
            if (MODE == 0)
                *(float4*)(g_agg + (size_t)(n0 + r) * HID + c0) = make_float4(0.f, 0.f, 0.f, 0.f);
        }
        __syncwarp();
    }
}

// ---------------- readout ----------------
__global__ void readout_kernel(const int* __restrict__ batch,
                               const float* __restrict__ o1w, const float* __restrict__ o1b,
                               const float* __restrict__ o2w, const float* __restrict__ o2b,
                               float* __restrict__ out) {
    __shared__ float o1s[HID * 64];
    __shared__ float o2s[64];
    __shared__ float xs[8][HID];
    for (int i = threadIdx.x; i < HID * 64; i += blockDim.x) o1s[i] = o1w[i];
    if (threadIdx.x < 64) o2s[threadIdx.x] = o2w[threadIdx.x];
    __syncthreads();

    const int wid = threadIdx.x >> 5, lane = threadIdx.x & 31;
    const int gw = blockIdx.x * 8 + wid, nw = gridDim.x * 8;
    const float b0 = o1b[lane], b1v = o1b[lane + 32];
    const float w20 = o2s[lane], w21 = o2s[lane + 32];
    const float ob = o2b[0];

    for (int n = gw; n < N_NODES; n += nw) {
        *(float4*)(&xs[wid][lane * 4]) = *(const float4*)(g_h + (size_t)n * HID + lane * 4);
        __syncwarp();
        float t0 = b0, t1 = b1v;
        #pragma unroll 8
        for (int k = 0; k < HID; k++) {
            float v = xs[wid][k];
            t0 += v * o1s[k * 64 + lane];
            t1 += v * o1s[k * 64 + lane + 32];
        }
        float p = sspf(t0) * w20 + sspf(t1) * w21;
        #pragma unroll
        for (int off = 16; off; off >>= 1) p += __shfl_down_sync(0xffffffffu, p, off);
        if (lane == 0) atomicAdd(&out[batch[n]], p + ob);
        __syncwarp();
    }
}

// ---------------- launch ----------------
extern "C" void kernel_launch(void* const* d_in, const int* in_sizes, int n_in,
                              void* d_out, int out_size) {
    const int*   z      = (const int*)  d_in[0];
    const float* pos    = (const float*)d_in[1];
    const int*   batch  = (const int*)  d_in[2];
    const int*   ei     = (const int*)  d_in[3];
    const float* eattr  = (const float*)d_in[4];
    const float* emb    = (const float*)d_in[5];
    const float* mlp_w1 = (const float*)d_in[6];
    const float* mlp_b1 = (const float*)d_in[7];
    const float* mlp_w2 = (const float*)d_in[8];
    const float* mlp_b2 = (const float*)d_in[9];
    const float* cf1_w  = (const float*)d_in[10];
    const float* cf2_w  = (const float*)d_in[11];
    const float* cf2_b  = (const float*)d_in[12];
    const float* lin_w  = (const float*)d_in[13];
    const float* lin_b  = (const float*)d_in[14];
    const float* o1w    = (const float*)d_in[15];
    const float* o1b    = (const float*)d_in[16];
    const float* o2w    = (const float*)d_in[17];
    const float* o2b    = (const float*)d_in[18];
    float* out = (float*)d_out;

    const int GEMM_SMEM = (HID * HID + HID + 8 * 512) * (int)sizeof(float);
    cudaFuncSetAttribute(edge_mma_kernel, cudaFuncAttributeMaxDynamicSharedMemorySize, EK_SMEM);
    cudaFuncSetAttribute(node_gemm<0>, cudaFuncAttributeMaxDynamicSharedMemorySize, GEMM_SMEM);
    cudaFuncSetAttribute(node_gemm<1>, cudaFuncAttributeMaxDynamicSharedMemorySize, GEMM_SMEM);
    cudaFuncSetAttribute(node_gemm<2>, cudaFuncAttributeMaxDynamicSharedMemorySize, GEMM_SMEM);

    float *ph, *pxh, *pagg, *ptmp;
    cudaGetSymbolAddress((void**)&ph,   g_h);
    cudaGetSymbolAddress((void**)&pxh,  g_xh);
    cudaGetSymbolAddress((void**)&pagg, g_agg);
    cudaGetSymbolAddress((void**)&ptmp, g_tmp);

    zero_out_kernel<<<1, 32>>>(out);
    embed_kernel<<<(N_NODES * HID + 255) / 256, 256>>>(z, emb);
    edge_pre_kernel<<<(N_EDGES + 255) / 256, 256>>>(ei, pos);

    for (int l = 0; l < 3; l++) {
        node_gemm<0><<<296, 256, GEMM_SMEM>>>(ph, cf1_w + (size_t)l * HID * HID, nullptr, pxh);
        edge_mma_kernel<<<296, 256, EK_SMEM>>>(ei, eattr,
                                               mlp_w1 + (size_t)l * NF * HID, mlp_b1 + (size_t)l * HID,
                                               mlp_w2 + (size_t)l * HID * HID, mlp_b2 + (size_t)l * HID);
        node_gemm<1><<<296, 256, GEMM_SMEM>>>(pagg, cf2_w + (size_t)l * HID * HID, cf2_b + (size_t)l * HID, ptmp);
        node_gemm<2><<<296, 256, GEMM_SMEM>>>(ptmp, lin_w + (size_t)l * HID * HID, lin_b + (size_t)l * HID, ph);
    }
    readout_kernel<<<592, 256>>>(batch, o1w, o1b, o2w, o2b, out);
}

// round 5
// speedup vs baseline: 4.9317x; 1.0315x over previous
#include <cuda_runtime.h>
#include <cuda_fp16.h>
#include <cstdint>
#include <math.h>

#define N_NODES 20000
#define N_EDGES 640000
#define HID 128
#define NB 3
#define NGS 47
#define NF 50
#define B_GRAPHS 16
#define LOG2F_ 0.69314718055994530942f
#define CUTF 10.0f
#define PI_F 3.14159265358979323846f
#define EDGE_TILES (N_EDGES / 128)   // 5000

#define SA1 72     // halves stride for A / W1 tiles (K=64 + 8 pad)
#define SA2 136    // halves stride for H / W2 tiles (K=128 + 8 pad)

// smem byte offsets for edge kernel
#define OFF_W1h 0                         // 128*72*2  = 18432
#define OFF_W2h 18432                     // 128*136*2 = 34816
#define OFF_A   53248                     // 128*72*2  = 18432
#define OFF_H   71680                     // 128*136*2 = 34816
#define OFF_B1  106496                    // 512
#define OFF_B2  107008                    // 512
#define EK_SMEM 107520                    // ~105KB -> 2 CTAs/SM

// ---------------- scratch ----------------
__device__ float g_h  [N_NODES * HID];
__device__ float g_xh [N_NODES * HID];
__device__ float g_agg[N_NODES * HID];
__device__ float g_ew [N_EDGES];
__device__ float g_Cc [N_EDGES];

__device__ __forceinline__ float sspf(float x) {
    float sp = (x > 15.f) ? x : log1pf(__expf(x));
    return sp - LOG2F_;
}
__device__ __forceinline__ uint32_t smem_to_u32(const void* p) {
    uint32_t a;
    asm("{ .reg .u64 t; cvta.to.shared.u64 t, %1; cvt.u32.u64 %0, t; }" : "=r"(a) : "l"(p));
    return a;
}
__device__ __forceinline__ void ldm_x4(uint32_t& r0, uint32_t& r1, uint32_t& r2, uint32_t& r3, uint32_t a) {
    asm volatile("ldmatrix.sync.aligned.m8n8.x4.shared.b16 {%0,%1,%2,%3}, [%4];"
                 : "=r"(r0), "=r"(r1), "=r"(r2), "=r"(r3) : "r"(a));
}
__device__ __forceinline__ void mma16816(float* c, uint32_t a0, uint32_t a1, uint32_t a2, uint32_t a3,
                                         uint32_t b0, uint32_t b1) {
    asm volatile("mma.sync.aligned.m16n8k16.row.col.f32.f16.f16.f32 "
                 "{%0,%1,%2,%3}, {%4,%5,%6,%7}, {%8,%9}, {%0,%1,%2,%3};"
                 : "+f"(c[0]), "+f"(c[1]), "+f"(c[2]), "+f"(c[3])
                 : "r"(a0), "r"(a1), "r"(a2), "r"(a3), "r"(b0), "r"(b1));
}

// ---------------- small kernels ----------------
__global__ void zero_out_kernel(float* out) {
    if (threadIdx.x < B_GRAPHS) out[threadIdx.x] = 0.f;
}
__global__ void edge_pre_kernel(const int* __restrict__ ei, const float* __restrict__ pos) {
    int e = blockIdx.x * blockDim.x + threadIdx.x;
    if (e < N_EDGES) {
        int r = ei[e], c = ei[N_EDGES + e];
        float dx = pos[r * 3 + 0] - pos[c * 3 + 0];
        float dy = pos[r * 3 + 1] - pos[c * 3 + 1];
        float dz = pos[r * 3 + 2] - pos[c * 3 + 2];
        float ew = sqrtf(dx * dx + dy * dy + dz * dz);
        g_ew[e] = ew;
        g_Cc[e] = 0.5f * (cosf(ew * (PI_F / CUTF)) + 1.f);
    }
}

// ---------------- node_init: h = emb[z]; xh = h @ cf1_0; agg = 0 ----------------
__global__ void __launch_bounds__(256)
node_init(const int* __restrict__ z, const float* __restrict__ emb,
          const float* __restrict__ W) {
    extern __shared__ float sm[];
    float* Ws = sm;                 // 16384
    float* xs = Ws + HID * HID;     // 8 warps * 512
    for (int i = threadIdx.x; i < HID * HID; i += blockDim.x) Ws[i] = W[i];
    __syncthreads();

    const int wid = threadIdx.x >> 5, lane = threadIdx.x & 31;
    float* xw = xs + wid * 512;
    const int gw = blockIdx.x * 8 + wid, nw = gridDim.x * 8;
    const int c0 = lane * 4;

    for (int gidx = gw; gidx < N_NODES / 4; gidx += nw) {
        int n0 = gidx * 4;
        #pragma unroll
        for (int j = 0; j < 4; j++) {
            int zr = z[n0 + j];
            float4 v = ((const float4*)(emb + (size_t)zr * HID))[lane];
            ((float4*)xw)[lane + 32 * j] = v;
            ((float4*)(g_h + (size_t)(n0 + j) * HID))[lane] = v;
            ((float4*)(g_agg + (size_t)(n0 + j) * HID))[lane] = make_float4(0.f, 0.f, 0.f, 0.f);
        }
        __syncwarp();
        float a[4][4];
        #pragma unroll
        for (int r = 0; r < 4; r++) { a[r][0] = a[r][1] = a[r][2] = a[r][3] = 0.f; }
        #pragma unroll 4
        for (int k = 0; k < HID; k++) {
            float4 w = *(const float4*)(Ws + k * HID + c0);
            #pragma unroll
            for (int r = 0; r < 4; r++) {
                float v = xw[r * HID + k];
                a[r][0] += v * w.x; a[r][1] += v * w.y; a[r][2] += v * w.z; a[r][3] += v * w.w;
            }
        }
        #pragma unroll
        for (int r = 0; r < 4; r++)
            *(float4*)(g_xh + (size_t)(n0 + r) * HID + c0) =
                make_float4(a[r][0], a[r][1], a[r][2], a[r][3]);
        __syncwarp();
    }
}

// ---------------- edge filter MLP: fp16 mma + ldmatrix, 2 CTAs/SM ----------------
__device__ __forceinline__ void featgen(half* Ah, const float* eattr, int e0, int tid,
                                        float step, float coeff) {
    int e = e0 + (tid >> 1);
    int seg = tid & 1;
    float ew = g_ew[e];
    half2* arow = (half2*)(Ah + (size_t)(tid >> 1) * SA1 + seg * 32);
    float f[32];
    if (seg == 0) {
        f[0] = eattr[e * NB + 0];
        f[1] = eattr[e * NB + 1];
        f[2] = eattr[e * NB + 2];
        #pragma unroll
        for (int j = 3; j < 32; j++) {
            float d = ew - (float)(j - 3) * step;
            f[j] = __expf(coeff * d * d);
        }
    } else {
        #pragma unroll
        for (int j = 0; j < 18; j++) {
            float d = ew - (float)(29 + j) * step;
            f[j] = __expf(coeff * d * d);
        }
        #pragma unroll
        for (int j = 18; j < 32; j++) f[j] = 0.f;
    }
    #pragma unroll
    for (int j = 0; j < 16; j++) arow[j] = __floats2half2_rn(f[2 * j], f[2 * j + 1]);
}

__global__ void __launch_bounds__(256, 2)
edge_mma_kernel(const int* __restrict__ ei, const float* __restrict__ eattr,
                const float* __restrict__ w1, const float* __restrict__ b1,
                const float* __restrict__ w2, const float* __restrict__ b2) {
    extern __shared__ char smem[];
    half* w1h = (half*)(smem + OFF_W1h);
    half* w2h = (half*)(smem + OFF_W2h);
    half* Ah  = (half*)(smem + OFF_A);
    half* Hh  = (half*)(smem + OFF_H);
    float* b1s = (float*)(smem + OFF_B1);
    float* b2s = (float*)(smem + OFF_B2);

    const int tid = threadIdx.x, wid = tid >> 5, lane = tid & 31;
    const int g = lane >> 2, tg = lane & 3;
    const int rt = wid & 3, nh = wid >> 2;

    for (int i = tid; i < 128 * 64; i += 256) {
        int n = i >> 6, k = i & 63;
        w1h[n * SA1 + k] = __float2half_rn((k < NF) ? w1[k * HID + n] : 0.f);
    }
    for (int i = tid; i < 128 * 128; i += 256) {
        int n = i >> 7, k = i & 127;
        w2h[n * SA2 + k] = __float2half_rn(w2[k * HID + n]);
    }
    if (tid < HID) { b1s[tid] = b1[tid]; b2s[tid] = b2[tid]; }

    const uint32_t aU  = smem_to_u32(Ah);
    const uint32_t hU  = smem_to_u32(Hh);
    const uint32_t w1U = smem_to_u32(w1h);
    const uint32_t w2U = smem_to_u32(w2h);

    const float step = CUTF / (float)(NGS - 1);
    const float coeff = -0.5f / (step * step);
    const int lrow = lane & 15;
    const int lkh  = (lane >> 4) << 3;

    featgen(Ah, eattr, blockIdx.x * 128, tid, step, coeff);
    __syncthreads();

    for (int t = blockIdx.x; t < EDGE_TILES; t += gridDim.x) {
        const int e0 = t * 128;
        // ---- prefetch edge meta (overlaps GEMMs) ----
        int rA[2], rB[2], cA[2], cB[2];
        float CA[2], CB[2];
        {
            int base = e0 + rt * 32 + g;
            #pragma unroll
            for (int mt = 0; mt < 2; mt++) {
                int ea = base + mt * 16, eb = ea + 8;
                rA[mt] = ei[ea];            rB[mt] = ei[eb];
                cA[mt] = ei[N_EDGES + ea];  cB[mt] = ei[N_EDGES + eb];
                CA[mt] = g_Cc[ea];          CB[mt] = g_Cc[eb];
            }
        }

        float acc[2][8][4];
        #pragma unroll
        for (int mt = 0; mt < 2; mt++)
            #pragma unroll
            for (int j = 0; j < 8; j++)
                #pragma unroll
                for (int q = 0; q < 4; q++) acc[mt][j][q] = 0.f;

        // ---- GEMM1 ----
        #pragma unroll
        for (int ks = 0; ks < 4; ks++) {
            const int k0 = ks * 16;
            uint32_t am[2][4];
            #pragma unroll
            for (int mt = 0; mt < 2; mt++) {
                uint32_t addr = aU + (uint32_t)(((rt * 32 + mt * 16 + lrow) * SA1 + k0 + lkh) << 1);
                ldm_x4(am[mt][0], am[mt][1], am[mt][2], am[mt][3], addr);
            }
            #pragma unroll
            for (int jj = 0; jj < 4; jj++) {
                uint32_t b0, b1r, b2r, b3;
                uint32_t addr = w1U + (uint32_t)(((nh * 64 + jj * 16 + lrow) * SA1 + k0 + lkh) << 1);
                ldm_x4(b0, b1r, b2r, b3, addr);
                #pragma unroll
                for (int mt = 0; mt < 2; mt++) {
                    mma16816(acc[mt][2 * jj],     am[mt][0], am[mt][1], am[mt][2], am[mt][3], b0,  b2r);
                    mma16816(acc[mt][2 * jj + 1], am[mt][0], am[mt][1], am[mt][2], am[mt][3], b1r, b3);
                }
            }
        }
        __syncthreads();

        // ---- epilogue1: H = fp16(ssp(D + b1)) ----
        #pragma unroll
        for (int mt = 0; mt < 2; mt++) {
            int r0 = rt * 32 + mt * 16 + g;
            #pragma unroll
            for (int j = 0; j < 8; j++) {
                int c = nh * 64 + j * 8 + tg * 2;
                float bx = b1s[c], by = b1s[c + 1];
                *(half2*)(Hh + (size_t)r0 * SA2 + c) =
                    __floats2half2_rn(sspf(acc[mt][j][0] + bx), sspf(acc[mt][j][1] + by));
                *(half2*)(Hh + (size_t)(r0 + 8) * SA2 + c) =
                    __floats2half2_rn(sspf(acc[mt][j][2] + bx), sspf(acc[mt][j][3] + by));
            }
        }
        __syncthreads();

        // ---- GEMM2 ----
        #pragma unroll
        for (int mt = 0; mt < 2; mt++)
            #pragma unroll
            for (int j = 0; j < 8; j++)
                #pragma unroll
                for (int q = 0; q < 4; q++) acc[mt][j][q] = 0.f;
        #pragma unroll
        for (int ks = 0; ks < 8; ks++) {
            const int k0 = ks * 16;
            uint32_t am[2][4];
            #pragma unroll
            for (int mt = 0; mt < 2; mt++) {
                uint32_t addr = hU + (uint32_t)(((rt * 32 + mt * 16 + lrow) * SA2 + k0 + lkh) << 1);
                ldm_x4(am[mt][0], am[mt][1], am[mt][2], am[mt][3], addr);
            }
            #pragma unroll
            for (int jj = 0; jj < 4; jj++) {
                uint32_t b0, b1r, b2r, b3;
                uint32_t addr = w2U + (uint32_t)(((nh * 64 + jj * 16 + lrow) * SA2 + k0 + lkh) << 1);
                ldm_x4(b0, b1r, b2r, b3, addr);
                #pragma unroll
                for (int mt = 0; mt < 2; mt++) {
                    mma16816(acc[mt][2 * jj],     am[mt][0], am[mt][1], am[mt][2], am[mt][3], b0,  b2r);
                    mma16816(acc[mt][2 * jj + 1], am[mt][0], am[mt][1], am[mt][2], am[mt][3], b1r, b3);
                }
            }
        }

        // feature gen for next tile overlaps epilogue (A is free)
        int tn = t + gridDim.x;
        if (tn < EDGE_TILES) featgen(Ah, eattr, tn * 128, tid, step, coeff);

        // ---- epilogue2: batched gather prefetch, then FMA + red ----
        #pragma unroll
        for (int mt = 0; mt < 2; mt++) {
            const float* xA = g_xh + (size_t)rA[mt] * HID;
            const float* xB = g_xh + (size_t)rB[mt] * HID;
            float2 va[8], vb[8];
            #pragma unroll
            for (int j = 0; j < 8; j++) {
                int c = nh * 64 + j * 8 + tg * 2;
                va[j] = *(const float2*)(xA + c);
                vb[j] = *(const float2*)(xB + c);
            }
            float* aA = g_agg + (size_t)cA[mt] * HID;
            float* aB = g_agg + (size_t)cB[mt] * HID;
            float Ca = CA[mt], Cb = CB[mt];
            #pragma unroll
            for (int j = 0; j < 8; j++) {
                int c = nh * 64 + j * 8 + tg * 2;
                float bx = b2s[c], by = b2s[c + 1];
                float p0 = (acc[mt][j][0] + bx) * Ca * va[j].x;
                float p1 = (acc[mt][j][1] + by) * Ca * va[j].y;
                asm volatile("red.global.add.v2.f32 [%0], {%1, %2};"
                             :: "l"(aA + c), "f"(p0), "f"(p1) : "memory");
                float q0 = (acc[mt][j][2] + bx) * Cb * vb[j].x;
                float q1 = (acc[mt][j][3] + by) * Cb * vb[j].y;
                asm volatile("red.global.add.v2.f32 [%0], {%1, %2};"
                             :: "l"(aB + c), "f"(q0), "f"(q1) : "memory");
            }
        }
        __syncthreads();
    }
}

// ---------------- fused node phase ----------------
// t = ssp(agg@cf2 + b); u = t@lin + b; h += u; agg = 0;
// LAST=0: xh = h @ cf1_next      LAST=1: readout into out
template <int LAST>
__global__ void __launch_bounds__(512, 1)
node_fused(const float* __restrict__ wA, const float* __restrict__ bA,
           const float* __restrict__ wB, const float* __restrict__ bB,
           const float* __restrict__ wC,
           const float* __restrict__ o1b, const float* __restrict__ o2w,
           const float* __restrict__ o2b,
           const int* __restrict__ batch, float* __restrict__ out) {
    extern __shared__ float sm[];
    float* WA = sm;                    // 16384
    float* WB = WA + 16384;            // 16384
    float* WC = WB + 16384;            // 16384 (cf1n) or 8192 (o1w)
    float* BAs = WC + 16384;           // 128
    float* BBs = BAs + 128;            // 128
    float* BOs = BBs + 128;            // 64
    float* O2s = BOs + 64;             // 64
    float* stage = O2s + 64;           // 16 warps * 512

    const int tid = threadIdx.x;
    for (int i = tid; i < HID * HID; i += 512) { WA[i] = wA[i]; WB[i] = wB[i]; }
    if (LAST) {
        for (int i = tid; i < HID * 64; i += 512) WC[i] = wC[i];
        if (tid < 64) { BOs[tid] = o1b[tid]; O2s[tid] = o2w[tid]; }
    } else {
        for (int i = tid; i < HID * HID; i += 512) WC[i] = wC[i];
    }
    if (tid < HID) { BAs[tid] = bA[tid]; BBs[tid] = bB[tid]; }
    __syncthreads();

    const int wid = tid >> 5, lane = tid & 31;
    float* xw = stage + wid * 512;
    const int gw = blockIdx.x * 16 + wid, nw = gridDim.x * 16;
    const int c0 = lane * 4;
    const float ob = LAST ? o2b[0] : 0.f;

    for (int gidx = gw; gidx < N_NODES / 4; gidx += nw) {
        int n0 = gidx * 4;
        // load agg rows, zero agg
        #pragma unroll
        for (int j = 0; j < 4; j++) {
            float4* ap = (float4*)(g_agg + (size_t)(n0 + j) * HID);
            ((float4*)xw)[lane + 32 * j] = ap[lane];
            ap[lane] = make_float4(0.f, 0.f, 0.f, 0.f);
        }
        __syncwarp();

        // GEMV A: t = ssp(agg @ cf2 + bA)
        float a[4][4];
        {
            float4 bv = *(const float4*)(BAs + c0);
            #pragma unroll
            for (int r = 0; r < 4; r++) { a[r][0] = bv.x; a[r][1] = bv.y; a[r][2] = bv.z; a[r][3] = bv.w; }
            #pragma unroll 4
            for (int k = 0; k < HID; k++) {
                float4 w = *(const float4*)(WA + k * HID + c0);
                #pragma unroll
                for (int r = 0; r < 4; r++) {
                    float v = xw[r * HID + k];
                    a[r][0] += v * w.x; a[r][1] += v * w.y; a[r][2] += v * w.z; a[r][3] += v * w.w;
                }
            }
        }
        __syncwarp();
        #pragma unroll
        for (int r = 0; r < 4; r++)
            *(float4*)(xw + r * HID + c0) =
                make_float4(sspf(a[r][0]), sspf(a[r][1]), sspf(a[r][2]), sspf(a[r][3]));
        __syncwarp();

        // GEMV B: h += t @ lin + bB
        {
            float4 bv = *(const float4*)(BBs + c0);
            #pragma unroll
            for (int r = 0; r < 4; r++) { a[r][0] = bv.x; a[r][1] = bv.y; a[r][2] = bv.z; a[r][3] = bv.w; }
            #pragma unroll 4
            for (int k = 0; k < HID; k++) {
                float4 w = *(const float4*)(WB + k * HID + c0);
                #pragma unroll
                for (int r = 0; r < 4; r++) {
                    float v = xw[r * HID + k];
                    a[r][0] += v * w.x; a[r][1] += v * w.y; a[r][2] += v * w.z; a[r][3] += v * w.w;
                }
            }
        }
        __syncwarp();
        #pragma unroll
        for (int r = 0; r < 4; r++) {
            float* hp = g_h + (size_t)(n0 + r) * HID + c0;
            float4 old = *(const float4*)hp;
            float4 hn = make_float4(old.x + a[r][0], old.y + a[r][1],
                                    old.z + a[r][2], old.w + a[r][3]);
            *(float4*)hp = hn;
            *(float4*)(xw + r * HID + c0) = hn;
        }
        __syncwarp();

        if (!LAST) {
            // GEMV C: xh = h @ cf1_next
            #pragma unroll
            for (int r = 0; r < 4; r++) { a[r][0] = a[r][1] = a[r][2] = a[r][3] = 0.f; }
            #pragma unroll 4
            for (int k = 0; k < HID; k++) {
                float4 w = *(const float4*)(WC + k * HID + c0);
                #pragma unroll
                for (int r = 0; r < 4; r++) {
                    float v = xw[r * HID + k];
                    a[r][0] += v * w.x; a[r][1] += v * w.y; a[r][2] += v * w.z; a[r][3] += v * w.w;
                }
            }
            #pragma unroll
            for (int r = 0; r < 4; r++)
                *(float4*)(g_xh + (size_t)(n0 + r) * HID + c0) =
                    make_float4(a[r][0], a[r][1], a[r][2], a[r][3]);
        } else {
            // readout: p = ssp(h@o1+b)@o2 + b2 -> atomicAdd(out[batch])
            #pragma unroll
            for (int r = 0; r < 4; r++) {
                float t0 = BOs[lane], t1 = BOs[lane + 32];
                #pragma unroll 8
                for (int k = 0; k < HID; k++) {
                    float v = xw[r * HID + k];
                    t0 += v * WC[k * 64 + lane];
                    t1 += v * WC[k * 64 + lane + 32];
                }
                float p = sspf(t0) * O2s[lane] + sspf(t1) * O2s[lane + 32];
                #pragma unroll
                for (int off = 16; off; off >>= 1) p += __shfl_down_sync(0xffffffffu, p, off);
                if (lane == 0) atomicAdd(&out[batch[n0 + r]], p + ob);
            }
        }
        __syncwarp();
    }
}

// ---------------- launch ----------------
extern "C" void kernel_launch(void* const* d_in, const int* in_sizes, int n_in,
                              void* d_out, int out_size) {
    const int*   z      = (const int*)  d_in[0];
    const float* pos    = (const float*)d_in[1];
    const int*   batch  = (const int*)  d_in[2];
    const int*   ei     = (const int*)  d_in[3];
    const float* eattr  = (const float*)d_in[4];
    const float* emb    = (const float*)d_in[5];
    const float* mlp_w1 = (const float*)d_in[6];
    const float* mlp_b1 = (const float*)d_in[7];
    const float* mlp_w2 = (const float*)d_in[8];
    const float* mlp_b2 = (const float*)d_in[9];
    const float* cf1_w  = (const float*)d_in[10];
    const float* cf2_w  = (const float*)d_in[11];
    const float* cf2_b  = (const float*)d_in[12];
    const float* lin_w  = (const float*)d_in[13];
    const float* lin_b  = (const float*)d_in[14];
    const float* o1w    = (const float*)d_in[15];
    const float* o1b    = (const float*)d_in[16];
    const float* o2w    = (const float*)d_in[17];
    const float* o2b    = (const float*)d_in[18];
    float* out = (float*)d_out;

    const int NI_SMEM = (HID * HID + 8 * 512) * (int)sizeof(float);
    const int NF_SMEM = (3 * HID * HID + 2 * HID + 128 + 16 * 512) * (int)sizeof(float);
    cudaFuncSetAttribute(edge_mma_kernel, cudaFuncAttributeMaxDynamicSharedMemorySize, EK_SMEM);
    cudaFuncSetAttribute(node_init,     cudaFuncAttributeMaxDynamicSharedMemorySize, NI_SMEM);
    cudaFuncSetAttribute(node_fused<0>, cudaFuncAttributeMaxDynamicSharedMemorySize, NF_SMEM);
    cudaFuncSetAttribute(node_fused<1>, cudaFuncAttributeMaxDynamicSharedMemorySize, NF_SMEM);

    zero_out_kernel<<<1, 32>>>(out);
    edge_pre_kernel<<<(N_EDGES + 255) / 256, 256>>>(ei, pos);
    node_init<<<296, 256, NI_SMEM>>>(z, emb, cf1_w);

    for (int l = 0; l < 3; l++) {
        edge_mma_kernel<<<296, 256, EK_SMEM>>>(ei, eattr,
                                               mlp_w1 + (size_t)l * NF * HID, mlp_b1 + (size_t)l * HID,
                                               mlp_w2 + (size_t)l * HID * HID, mlp_b2 + (size_t)l * HID);
        if (l < 2) {
            node_fused<0><<<148, 512, NF_SMEM>>>(
                cf2_w + (size_t)l * HID * HID, cf2_b + (size_t)l * HID,
                lin_w + (size_t)l * HID * HID, lin_b + (size_t)l * HID,
                cf1_w + (size_t)(l + 1) * HID * HID,
                nullptr, nullptr, nullptr, batch, out);
        } else {
            node_fused<1><<<148, 512, NF_SMEM>>>(
                cf2_w + (size_t)l * HID * HID, cf2_b + (size_t)l * HID,
                lin_w + (size_t)l * HID * HID, lin_b + (size_t)l * HID,
                o1w, o1b, o2w, o2b, batch, out);
        }
    }
}

// round 6
// speedup vs baseline: 5.8097x; 1.1780x over previous
#include <cuda_runtime.h>
#include <cuda_fp16.h>
#include <cstdint>
#include <math.h>

#define N_NODES 20000
#define N_EDGES 640000
#define HID 128
#define NB 3
#define NGS 47
#define NF 50
#define B_GRAPHS 16
#define LOG2F_ 0.69314718055994530942f
#define CUTF 10.0f
#define PI_F 3.14159265358979323846f
#define EDGE_TILES (N_EDGES / 128)   // 5000

#define SA1 72     // halves stride for A / W1 tiles (K=64 + 8 pad)
#define SA2 136    // halves stride for H / W2 tiles (K=128 + 8 pad)

// smem byte offsets for edge kernel
#define OFF_W1h 0                         // 128*72*2  = 18432
#define OFF_W2h 18432                     // 128*136*2 = 34816
#define OFF_A   53248                     // 128*72*2  = 18432
#define OFF_H   71680                     // 128*136*2 = 34816
#define OFF_B1  106496                    // 512
#define OFF_B2  107008                    // 512
#define EK_SMEM 107520                    // ~105KB -> 2 CTAs/SM

// ---------------- scratch ----------------
__device__ float g_h  [N_NODES * HID];
__device__ float g_xh [N_NODES * HID];
__device__ float g_agg[N_NODES * HID];
__device__ float g_Cc [N_EDGES];
__device__ half  g_feat[(size_t)N_EDGES * 64];   // precomputed fp16 edge features

// fast exact softplus(x) - log(2): max(x,0) + log(1+exp(-|x|)) - log2
__device__ __forceinline__ float sspf(float x) {
    float e = __expf(-fabsf(x));
    return fmaxf(x, 0.f) + __logf(1.f + e) - LOG2F_;
}
__device__ __forceinline__ uint32_t smem_to_u32(const void* p) {
    uint32_t a;
    asm("{ .reg .u64 t; cvta.to.shared.u64 t, %1; cvt.u32.u64 %0, t; }" : "=r"(a) : "l"(p));
    return a;
}
__device__ __forceinline__ void ldm_x4(uint32_t& r0, uint32_t& r1, uint32_t& r2, uint32_t& r3, uint32_t a) {
    asm volatile("ldmatrix.sync.aligned.m8n8.x4.shared.b16 {%0,%1,%2,%3}, [%4];"
                 : "=r"(r0), "=r"(r1), "=r"(r2), "=r"(r3) : "r"(a));
}
__device__ __forceinline__ void mma16816(float* c, uint32_t a0, uint32_t a1, uint32_t a2, uint32_t a3,
                                         uint32_t b0, uint32_t b1) {
    asm volatile("mma.sync.aligned.m16n8k16.row.col.f32.f16.f16.f32 "
                 "{%0,%1,%2,%3}, {%4,%5,%6,%7}, {%8,%9}, {%0,%1,%2,%3};"
                 : "+f"(c[0]), "+f"(c[1]), "+f"(c[2]), "+f"(c[3])
                 : "r"(a0), "r"(a1), "r"(a2), "r"(a3), "r"(b0), "r"(b1));
}

// ---------------- small kernels ----------------
__global__ void zero_out_kernel(float* out) {
    if (threadIdx.x < B_GRAPHS) out[threadIdx.x] = 0.f;
}

// edge_pre: 2 threads per edge. Computes C(e) and the fp16 feature row (64 halves).
__global__ void edge_pre_kernel(const int* __restrict__ ei, const float* __restrict__ pos,
                                const float* __restrict__ eattr) {
    int t = blockIdx.x * blockDim.x + threadIdx.x;
    int e = t >> 1, seg = t & 1;
    if (e >= N_EDGES) return;
    int r = ei[e], c = ei[N_EDGES + e];
    float dx = pos[r * 3 + 0] - pos[c * 3 + 0];
    float dy = pos[r * 3 + 1] - pos[c * 3 + 1];
    float dz = pos[r * 3 + 2] - pos[c * 3 + 2];
    float ew = sqrtf(dx * dx + dy * dy + dz * dz);
    const float step = CUTF / (float)(NGS - 1);
    const float coeff = -0.5f / (step * step);

    float f[32];
    if (seg == 0) {
        g_Cc[e] = 0.5f * (cosf(ew * (PI_F / CUTF)) + 1.f);
        f[0] = eattr[e * NB + 0];
        f[1] = eattr[e * NB + 1];
        f[2] = eattr[e * NB + 2];
        #pragma unroll
        for (int j = 3; j < 32; j++) {
            float d = ew - (float)(j - 3) * step;
            f[j] = __expf(coeff * d * d);
        }
    } else {
        #pragma unroll
        for (int j = 0; j < 18; j++) {
            float d = ew - (float)(29 + j) * step;
            f[j] = __expf(coeff * d * d);
        }
        #pragma unroll
        for (int j = 18; j < 32; j++) f[j] = 0.f;
    }
    half2 tmp[16];
    #pragma unroll
    for (int j = 0; j < 16; j++) tmp[j] = __floats2half2_rn(f[2 * j], f[2 * j + 1]);
    uint4* dst = (uint4*)(g_feat + (size_t)e * 64 + seg * 32);
    #pragma unroll
    for (int j = 0; j < 4; j++) dst[j] = ((uint4*)tmp)[j];
}

// ---------------- node_init: h = emb[z]; xh = h @ cf1_0; agg = 0 ----------------
__global__ void __launch_bounds__(256)
node_init(const int* __restrict__ z, const float* __restrict__ emb,
          const float* __restrict__ W) {
    extern __shared__ float sm[];
    float* Ws = sm;
    float* xs = Ws + HID * HID;
    for (int i = threadIdx.x; i < HID * HID; i += blockDim.x) Ws[i] = W[i];
    __syncthreads();

    const int wid = threadIdx.x >> 5, lane = threadIdx.x & 31;
    float* xw = xs + wid * 512;
    const int gw = blockIdx.x * 8 + wid, nw = gridDim.x * 8;
    const int c0 = lane * 4;

    for (int gidx = gw; gidx < N_NODES / 4; gidx += nw) {
        int n0 = gidx * 4;
        #pragma unroll
        for (int j = 0; j < 4; j++) {
            int zr = z[n0 + j];
            float4 v = ((const float4*)(emb + (size_t)zr * HID))[lane];
            ((float4*)xw)[lane + 32 * j] = v;
            ((float4*)(g_h + (size_t)(n0 + j) * HID))[lane] = v;
            ((float4*)(g_agg + (size_t)(n0 + j) * HID))[lane] = make_float4(0.f, 0.f, 0.f, 0.f);
        }
        __syncwarp();
        float a[4][4];
        #pragma unroll
        for (int r = 0; r < 4; r++) { a[r][0] = a[r][1] = a[r][2] = a[r][3] = 0.f; }
        #pragma unroll 4
        for (int k = 0; k < HID; k++) {
            float4 w = *(const float4*)(Ws + k * HID + c0);
            #pragma unroll
            for (int r = 0; r < 4; r++) {
                float v = xw[r * HID + k];
                a[r][0] += v * w.x; a[r][1] += v * w.y; a[r][2] += v * w.z; a[r][3] += v * w.w;
            }
        }
        #pragma unroll
        for (int r = 0; r < 4; r++)
            *(float4*)(g_xh + (size_t)(n0 + r) * HID + c0) =
                make_float4(a[r][0], a[r][1], a[r][2], a[r][3]);
        __syncwarp();
    }
}

// ---------------- edge filter MLP: fp16 mma + ldmatrix, 2 CTAs/SM ----------------
__global__ void __launch_bounds__(256, 2)
edge_mma_kernel(const int* __restrict__ ei,
                const float* __restrict__ w1, const float* __restrict__ b1,
                const float* __restrict__ w2, const float* __restrict__ b2) {
    extern __shared__ char smem[];
    half* w1h = (half*)(smem + OFF_W1h);
    half* w2h = (half*)(smem + OFF_W2h);
    half* Ah  = (half*)(smem + OFF_A);
    half* Hh  = (half*)(smem + OFF_H);
    float* b1s = (float*)(smem + OFF_B1);
    float* b2s = (float*)(smem + OFF_B2);

    const int tid = threadIdx.x, wid = tid >> 5, lane = tid & 31;
    const int g = lane >> 2, tg = lane & 3;
    const int rt = wid & 3, nh = wid >> 2;
    const int aedge = tid >> 1, aseg = tid & 1;   // A-tile copy geometry

    for (int i = tid; i < 128 * 64; i += 256) {
        int n = i >> 6, k = i & 63;
        w1h[n * SA1 + k] = __float2half_rn((k < NF) ? w1[k * HID + n] : 0.f);
    }
    for (int i = tid; i < 128 * 128; i += 256) {
        int n = i >> 7, k = i & 127;
        w2h[n * SA2 + k] = __float2half_rn(w2[k * HID + n]);
    }
    if (tid < HID) { b1s[tid] = b1[tid]; b2s[tid] = b2[tid]; }

    const uint32_t aU  = smem_to_u32(Ah);
    const uint32_t hU  = smem_to_u32(Hh);
    const uint32_t w1U = smem_to_u32(w1h);
    const uint32_t w2U = smem_to_u32(w2h);
    const int lrow = lane & 15;
    const int lkh  = (lane >> 4) << 3;

    uint4* aDst = (uint4*)(Ah + aedge * SA1 + aseg * 32);

    // preload first A tile
    {
        const uint4* src = (const uint4*)(g_feat + ((size_t)blockIdx.x * 128 + aedge) * 64 + aseg * 32);
        #pragma unroll
        for (int j = 0; j < 4; j++) aDst[j] = src[j];
    }
    __syncthreads();

    for (int t = blockIdx.x; t < EDGE_TILES; t += gridDim.x) {
        const int e0 = t * 128;
        // ---- prefetch edge meta (overlaps GEMMs) ----
        int rA[2], rB[2], cA[2], cB[2];
        float CA[2], CB[2];
        {
            int base = e0 + rt * 32 + g;
            #pragma unroll
            for (int mt = 0; mt < 2; mt++) {
                int ea = base + mt * 16, eb = ea + 8;
                rA[mt] = ei[ea];            rB[mt] = ei[eb];
                cA[mt] = ei[N_EDGES + ea];  cB[mt] = ei[N_EDGES + eb];
                CA[mt] = g_Cc[ea];          CB[mt] = g_Cc[eb];
            }
        }

        float acc[2][8][4];
        #pragma unroll
        for (int mt = 0; mt < 2; mt++)
            #pragma unroll
            for (int j = 0; j < 8; j++)
                #pragma unroll
                for (int q = 0; q < 4; q++) acc[mt][j][q] = 0.f;

        // ---- GEMM1 ----
        #pragma unroll
        for (int ks = 0; ks < 4; ks++) {
            const int k0 = ks * 16;
            uint32_t am[2][4];
            #pragma unroll
            for (int mt = 0; mt < 2; mt++) {
                uint32_t addr = aU + (uint32_t)(((rt * 32 + mt * 16 + lrow) * SA1 + k0 + lkh) << 1);
                ldm_x4(am[mt][0], am[mt][1], am[mt][2], am[mt][3], addr);
            }
            #pragma unroll
            for (int jj = 0; jj < 4; jj++) {
                uint32_t b0, b1r, b2r, b3;
                uint32_t addr = w1U + (uint32_t)(((nh * 64 + jj * 16 + lrow) * SA1 + k0 + lkh) << 1);
                ldm_x4(b0, b1r, b2r, b3, addr);
                #pragma unroll
                for (int mt = 0; mt < 2; mt++) {
                    mma16816(acc[mt][2 * jj],     am[mt][0], am[mt][1], am[mt][2], am[mt][3], b0,  b2r);
                    mma16816(acc[mt][2 * jj + 1], am[mt][0], am[mt][1], am[mt][2], am[mt][3], b1r, b3);
                }
            }
        }
        __syncthreads();   // A consumed, H(prev) consumed

        // ---- epilogue1: H = fp16(ssp(D + b1)) ----
        #pragma unroll
        for (int mt = 0; mt < 2; mt++) {
            int r0 = rt * 32 + mt * 16 + g;
            #pragma unroll
            for (int j = 0; j < 8; j++) {
                int c = nh * 64 + j * 8 + tg * 2;
                float bx = b1s[c], by = b1s[c + 1];
                *(half2*)(Hh + (size_t)r0 * SA2 + c) =
                    __floats2half2_rn(sspf(acc[mt][j][0] + bx), sspf(acc[mt][j][1] + by));
                *(half2*)(Hh + (size_t)(r0 + 8) * SA2 + c) =
                    __floats2half2_rn(sspf(acc[mt][j][2] + bx), sspf(acc[mt][j][3] + by));
            }
        }

        // prefetch next A tile into regs (latency hides under GEMM2)
        uint4 ap[4];
        const int tn = t + gridDim.x;
        if (tn < EDGE_TILES) {
            const uint4* src = (const uint4*)(g_feat + ((size_t)tn * 128 + aedge) * 64 + aseg * 32);
            #pragma unroll
            for (int j = 0; j < 4; j++) ap[j] = src[j];
        }
        __syncthreads();   // H ready

        // ---- GEMM2 ----
        #pragma unroll
        for (int mt = 0; mt < 2; mt++)
            #pragma unroll
            for (int j = 0; j < 8; j++)
                #pragma unroll
                for (int q = 0; q < 4; q++) acc[mt][j][q] = 0.f;
        #pragma unroll
        for (int ks = 0; ks < 8; ks++) {
            const int k0 = ks * 16;
            uint32_t am[2][4];
            #pragma unroll
            for (int mt = 0; mt < 2; mt++) {
                uint32_t addr = hU + (uint32_t)(((rt * 32 + mt * 16 + lrow) * SA2 + k0 + lkh) << 1);
                ldm_x4(am[mt][0], am[mt][1], am[mt][2], am[mt][3], addr);
            }
            #pragma unroll
            for (int jj = 0; jj < 4; jj++) {
                uint32_t b0, b1r, b2r, b3;
                uint32_t addr = w2U + (uint32_t)(((nh * 64 + jj * 16 + lrow) * SA2 + k0 + lkh) << 1);
                ldm_x4(b0, b1r, b2r, b3, addr);
                #pragma unroll
                for (int mt = 0; mt < 2; mt++) {
                    mma16816(acc[mt][2 * jj],     am[mt][0], am[mt][1], am[mt][2], am[mt][3], b0,  b2r);
                    mma16816(acc[mt][2 * jj + 1], am[mt][0], am[mt][1], am[mt][2], am[mt][3], b1r, b3);
                }
            }
        }

        // store next A tile (A buffer free since GEMM1 sync)
        if (tn < EDGE_TILES) {
            #pragma unroll
            for (int j = 0; j < 4; j++) aDst[j] = ap[j];
        }

        // ---- epilogue2: batched gather prefetch, then FMA + red ----
        #pragma unroll
        for (int mt = 0; mt < 2; mt++) {
            const float* xA = g_xh + (size_t)rA[mt] * HID;
            const float* xB = g_xh + (size_t)rB[mt] * HID;
            float2 va[8], vb[8];
            #pragma unroll
            for (int j = 0; j < 8; j++) {
                int c = nh * 64 + j * 8 + tg * 2;
                va[j] = *(const float2*)(xA + c);
                vb[j] = *(const float2*)(xB + c);
            }
            float* aA = g_agg + (size_t)cA[mt] * HID;
            float* aB = g_agg + (size_t)cB[mt] * HID;
            float Ca = CA[mt], Cb = CB[mt];
            #pragma unroll
            for (int j = 0; j < 8; j++) {
                int c = nh * 64 + j * 8 + tg * 2;
                float bx = b2s[c], by = b2s[c + 1];
                float p0 = (acc[mt][j][0] + bx) * Ca * va[j].x;
                float p1 = (acc[mt][j][1] + by) * Ca * va[j].y;
                asm volatile("red.global.add.v2.f32 [%0], {%1, %2};"
                             :: "l"(aA + c), "f"(p0), "f"(p1) : "memory");
                float q0 = (acc[mt][j][2] + bx) * Cb * vb[j].x;
                float q1 = (acc[mt][j][3] + by) * Cb * vb[j].y;
                asm volatile("red.global.add.v2.f32 [%0], {%1, %2};"
                             :: "l"(aB + c), "f"(q0), "f"(q1) : "memory");
            }
        }
        __syncthreads();   // A(t+1) ready; H free
    }
}

// ---------------- fused node phase ----------------
template <int LAST>
__global__ void __launch_bounds__(512, 1)
node_fused(const float* __restrict__ wA, const float* __restrict__ bA,
           const float* __restrict__ wB, const float* __restrict__ bB,
           const float* __restrict__ wC,
           const float* __restrict__ o1b, const float* __restrict__ o2w,
           const float* __restrict__ o2b,
           const int* __restrict__ batch, float* __restrict__ out) {
    extern __shared__ float sm[];
    float* WA = sm;
    float* WB = WA + 16384;
    float* WC = WB + 16384;
    float* BAs = WC + 16384;
    float* BBs = BAs + 128;
    float* BOs = BBs + 128;
    float* O2s = BOs + 64;
    float* stage = O2s + 64;

    const int tid = threadIdx.x;
    for (int i = tid; i < HID * HID; i += 512) { WA[i] = wA[i]; WB[i] = wB[i]; }
    if (LAST) {
        for (int i = tid; i < HID * 64; i += 512) WC[i] = wC[i];
        if (tid < 64) { BOs[tid] = o1b[tid]; O2s[tid] = o2w[tid]; }
    } else {
        for (int i = tid; i < HID * HID; i += 512) WC[i] = wC[i];
    }
    if (tid < HID) { BAs[tid] = bA[tid]; BBs[tid] = bB[tid]; }
    __syncthreads();

    const int wid = tid >> 5, lane = tid & 31;
    float* xw = stage + wid * 512;
    const int gw = blockIdx.x * 16 + wid, nw = gridDim.x * 16;
    const int c0 = lane * 4;
    const float ob = LAST ? o2b[0] : 0.f;

    for (int gidx = gw; gidx < N_NODES / 4; gidx += nw) {
        int n0 = gidx * 4;
        #pragma unroll
        for (int j = 0; j < 4; j++) {
            float4* ap = (float4*)(g_agg + (size_t)(n0 + j) * HID);
            ((float4*)xw)[lane + 32 * j] = ap[lane];
            ap[lane] = make_float4(0.f, 0.f, 0.f, 0.f);
        }
        __syncwarp();

        float a[4][4];
        {
            float4 bv = *(const float4*)(BAs + c0);
            #pragma unroll
            for (int r = 0; r < 4; r++) { a[r][0] = bv.x; a[r][1] = bv.y; a[r][2] = bv.z; a[r][3] = bv.w; }
            #pragma unroll 4
            for (int k = 0; k < HID; k++) {
                float4 w = *(const float4*)(WA + k * HID + c0);
                #pragma unroll
                for (int r = 0; r < 4; r++) {
                    float v = xw[r * HID + k];
                    a[r][0] += v * w.x; a[r][1] += v * w.y; a[r][2] += v * w.z; a[r][3] += v * w.w;
                }
            }
        }
        __syncwarp();
        #pragma unroll
        for (int r = 0; r < 4; r++)
            *(float4*)(xw + r * HID + c0) =
                make_float4(sspf(a[r][0]), sspf(a[r][1]), sspf(a[r][2]), sspf(a[r][3]));
        __syncwarp();

        {
            float4 bv = *(const float4*)(BBs + c0);
            #pragma unroll
            for (int r = 0; r < 4; r++) { a[r][0] = bv.x; a[r][1] = bv.y; a[r][2] = bv.z; a[r][3] = bv.w; }
            #pragma unroll 4
            for (int k = 0; k < HID; k++) {
                float4 w = *(const float4*)(WB + k * HID + c0);
                #pragma unroll
                for (int r = 0; r < 4; r++) {
                    float v = xw[r * HID + k];
                    a[r][0] += v * w.x; a[r][1] += v * w.y; a[r][2] += v * w.z; a[r][3] += v * w.w;
                }
            }
        }
        __syncwarp();
        #pragma unroll
        for (int r = 0; r < 4; r++) {
            float* hp = g_h + (size_t)(n0 + r) * HID + c0;
            float4 old = *(const float4*)hp;
            float4 hn = make_float4(old.x + a[r][0], old.y + a[r][1],
                                    old.z + a[r][2], old.w + a[r][3]);
            *(float4*)hp = hn;
            *(float4*)(xw + r * HID + c0) = hn;
        }
        __syncwarp();

        if (!LAST) {
            #pragma unroll
            for (int r = 0; r < 4; r++) { a[r][0] = a[r][1] = a[r][2] = a[r][3] = 0.f; }
            #pragma unroll 4
            for (int k = 0; k < HID; k++) {
                float4 w = *(const float4*)(WC + k * HID + c0);
                #pragma unroll
                for (int r = 0; r < 4; r++) {
                    float v = xw[r * HID + k];
                    a[r][0] += v * w.x; a[r][1] += v * w.y; a[r][2] += v * w.z; a[r][3] += v * w.w;
                }
            }
            #pragma unroll
            for (int r = 0; r < 4; r++)
                *(float4*)(g_xh + (size_t)(n0 + r) * HID + c0) =
                    make_float4(a[r][0], a[r][1], a[r][2], a[r][3]);
        } else {
            #pragma unroll
            for (int r = 0; r < 4; r++) {
                float t0 = BOs[lane], t1 = BOs[lane + 32];
                #pragma unroll 8
                for (int k = 0; k < HID; k++) {
                    float v = xw[r * HID + k];
                    t0 += v * WC[k * 64 + lane];
                    t1 += v * WC[k * 64 + lane + 32];
                }
                float p = sspf(t0) * O2s[lane] + sspf(t1) * O2s[lane + 32];
                #pragma unroll
                for (int off = 16; off; off >>= 1) p += __shfl_down_sync(0xffffffffu, p, off);
                if (lane == 0) atomicAdd(&out[batch[n0 + r]], p + ob);
            }
        }
        __syncwarp();
    }
}

// ---------------- launch ----------------
extern "C" void kernel_launch(void* const* d_in, const int* in_sizes, int n_in,
                              void* d_out, int out_size) {
    const int*   z      = (const int*)  d_in[0];
    const float* pos    = (const float*)d_in[1];
    const int*   batch  = (const int*)  d_in[2];
    const int*   ei     = (const int*)  d_in[3];
    const float* eattr  = (const float*)d_in[4];
    const float* emb    = (const float*)d_in[5];
    const float* mlp_w1 = (const float*)d_in[6];
    const float* mlp_b1 = (const float*)d_in[7];
    const float* mlp_w2 = (const float*)d_in[8];
    const float* mlp_b2 = (const float*)d_in[9];
    const float* cf1_w  = (const float*)d_in[10];
    const float* cf2_w  = (const float*)d_in[11];
    const float* cf2_b  = (const float*)d_in[12];
    const float* lin_w  = (const float*)d_in[13];
    const float* lin_b  = (const float*)d_in[14];
    const float* o1w    = (const float*)d_in[15];
    const float* o1b    = (const float*)d_in[16];
    const float* o2w    = (const float*)d_in[17];
    const float* o2b    = (const float*)d_in[18];
    float* out = (float*)d_out;

    const int NI_SMEM = (HID * HID + 8 * 512) * (int)sizeof(float);
    const int NF_SMEM = (3 * HID * HID + 2 * HID + 128 + 16 * 512) * (int)sizeof(float);
    cudaFuncSetAttribute(edge_mma_kernel, cudaFuncAttributeMaxDynamicSharedMemorySize, EK_SMEM);
    cudaFuncSetAttribute(node_init,     cudaFuncAttributeMaxDynamicSharedMemorySize, NI_SMEM);
    cudaFuncSetAttribute(node_fused<0>, cudaFuncAttributeMaxDynamicSharedMemorySize, NF_SMEM);
    cudaFuncSetAttribute(node_fused<1>, cudaFuncAttributeMaxDynamicSharedMemorySize, NF_SMEM);

    zero_out_kernel<<<1, 32>>>(out);
    edge_pre_kernel<<<(2 * N_EDGES + 255) / 256, 256>>>(ei, pos, eattr);
    node_init<<<296, 256, NI_SMEM>>>(z, emb, cf1_w);

    for (int l = 0; l < 3; l++) {
        edge_mma_kernel<<<296, 256, EK_SMEM>>>(ei,
                                               mlp_w1 + (size_t)l * NF * HID, mlp_b1 + (size_t)l * HID,
                                               mlp_w2 + (size_t)l * HID * HID, mlp_b2 + (size_t)l * HID);
        if (l < 2) {
            node_fused<0><<<148, 512, NF_SMEM>>>(
                cf2_w + (size_t)l * HID * HID, cf2_b + (size_t)l * HID,
                lin_w + (size_t)l * HID * HID, lin_b + (size_t)l * HID,
                cf1_w + (size_t)(l + 1) * HID * HID,
                nullptr, nullptr, nullptr, batch, out);
        } else {
            node_fused<1><<<148, 512, NF_SMEM>>>(
                cf2_w + (size_t)l * HID * HID, cf2_b + (size_t)l * HID,
                lin_w + (size_t)l * HID * HID, lin_b + (size_t)l * HID,
                o1w, o1b, o2w, o2b, batch, out);
        }
    }
}

// round 7
// speedup vs baseline: 5.9142x; 1.0180x over previous
#include <cuda_runtime.h>
#include <cuda_fp16.h>
#include <cstdint>
#include <math.h>

#define N_NODES 20000
#define N_PAD   20096            // 157 * 128
#define NT_TILES 157
#define N_EDGES 640000
#define HID 128
#define NB 3
#define NGS 47
#define NF 50
#define B_GRAPHS 16
#define LOG2F_ 0.69314718055994530942f
#define CUTF 10.0f
#define PI_F 3.14159265358979323846f
#define EDGE_TILES (N_EDGES / 128)   // 5000

#define SA1 72     // halves stride for A / W1 tiles (K=64 + 8 pad)
#define SA2 136    // halves stride for K=128 tiles (+8 pad)

// ---- edge kernel smem byte offsets ----
#define OFF_W1h 0                         // 128*72*2  = 18432
#define OFF_W2h 18432                     // 128*136*2 = 34816
#define OFF_A   53248                     // 18432
#define OFF_H   71680                     // 34816
#define OFF_B1  106496                    // 512
#define OFF_B2  107008                    // 512
#define EK_SMEM 107520                    // 2 CTAs/SM

// ---- node kernel smem byte offsets ----
#define NM_WA  0                          // 34816
#define NM_WB  34816                      // 34816
#define NM_WC  69632                      // 34816
#define NM_AT  104448                     // 34816
#define NM_HT  139264                     // 34816
#define NM_BA  174080                     // 512
#define NM_BB  174592                     // 512
#define NM_BO  175104                     // 256
#define NM_O2  175360                     // 256
#define NM_SMEM 175616

// ---------------- scratch ----------------
__device__ float g_h  [N_PAD * HID];
__device__ float g_xh [N_PAD * HID];
__device__ float g_agg[N_PAD * HID];
__device__ float g_Cc [N_EDGES];
__device__ half  g_feat[(size_t)N_EDGES * 64];

// fast exact softplus(x) - log(2)
__device__ __forceinline__ float sspf(float x) {
    float e = __expf(-fabsf(x));
    return fmaxf(x, 0.f) + __logf(1.f + e) - LOG2F_;
}
__device__ __forceinline__ uint32_t smem_to_u32(const void* p) {
    uint32_t a;
    asm("{ .reg .u64 t; cvta.to.shared.u64 t, %1; cvt.u32.u64 %0, t; }" : "=r"(a) : "l"(p));
    return a;
}
__device__ __forceinline__ void ldm_x4(uint32_t& r0, uint32_t& r1, uint32_t& r2, uint32_t& r3, uint32_t a) {
    asm volatile("ldmatrix.sync.aligned.m8n8.x4.shared.b16 {%0,%1,%2,%3}, [%4];"
                 : "=r"(r0), "=r"(r1), "=r"(r2), "=r"(r3) : "r"(a));
}
__device__ __forceinline__ void mma16816(float* c, uint32_t a0, uint32_t a1, uint32_t a2, uint32_t a3,
                                         uint32_t b0, uint32_t b1) {
    asm volatile("mma.sync.aligned.m16n8k16.row.col.f32.f16.f16.f32 "
                 "{%0,%1,%2,%3}, {%4,%5,%6,%7}, {%8,%9}, {%0,%1,%2,%3};"
                 : "+f"(c[0]), "+f"(c[1]), "+f"(c[2]), "+f"(c[3])
                 : "r"(a0), "r"(a1), "r"(a2), "r"(a3), "r"(b0), "r"(b1));
}

// ---------------- small kernels ----------------
__global__ void zero_out_kernel(float* out) {
    if (threadIdx.x < B_GRAPHS) out[threadIdx.x] = 0.f;
}

__global__ void edge_pre_kernel(const int* __restrict__ ei, const float* __restrict__ pos,
                                const float* __restrict__ eattr) {
    int t = blockIdx.x * blockDim.x + threadIdx.x;
    int e = t >> 1, seg = t & 1;
    if (e >= N_EDGES) return;
    int r = ei[e], c = ei[N_EDGES + e];
    float dx = pos[r * 3 + 0] - pos[c * 3 + 0];
    float dy = pos[r * 3 + 1] - pos[c * 3 + 1];
    float dz = pos[r * 3 + 2] - pos[c * 3 + 2];
    float ew = sqrtf(dx * dx + dy * dy + dz * dz);
    const float step = CUTF / (float)(NGS - 1);
    const float coeff = -0.5f / (step * step);

    float f[32];
    if (seg == 0) {
        g_Cc[e] = 0.5f * (cosf(ew * (PI_F / CUTF)) + 1.f);
        f[0] = eattr[e * NB + 0];
        f[1] = eattr[e * NB + 1];
        f[2] = eattr[e * NB + 2];
        #pragma unroll
        for (int j = 3; j < 32; j++) {
            float d = ew - (float)(j - 3) * step;
            f[j] = __expf(coeff * d * d);
        }
    } else {
        #pragma unroll
        for (int j = 0; j < 18; j++) {
            float d = ew - (float)(29 + j) * step;
            f[j] = __expf(coeff * d * d);
        }
        #pragma unroll
        for (int j = 18; j < 32; j++) f[j] = 0.f;
    }
    half2 tmp[16];
    #pragma unroll
    for (int j = 0; j < 16; j++) tmp[j] = __floats2half2_rn(f[2 * j], f[2 * j + 1]);
    uint4* dst = (uint4*)(g_feat + (size_t)e * 64 + seg * 32);
    #pragma unroll
    for (int j = 0; j < 4; j++) dst[j] = ((uint4*)tmp)[j];
}

// ---------------- node_init: h = emb[z]; xh = h @ cf1_0; agg = 0 (padded) ----------------
__global__ void __launch_bounds__(256)
node_init(const int* __restrict__ z, const float* __restrict__ emb,
          const float* __restrict__ W) {
    extern __shared__ float sm[];
    float* Ws = sm;
    float* xs = Ws + HID * HID;
    for (int i = threadIdx.x; i < HID * HID; i += blockDim.x) Ws[i] = W[i];
    __syncthreads();

    const int wid = threadIdx.x >> 5, lane = threadIdx.x & 31;
    float* xw = xs + wid * 512;
    const int gw = blockIdx.x * 8 + wid, nw = gridDim.x * 8;
    const int c0 = lane * 4;

    for (int gidx = gw; gidx < N_PAD / 4; gidx += nw) {
        int n0 = gidx * 4;
        #pragma unroll
        for (int j = 0; j < 4; j++) {
            int nn = n0 + j;
            float4 v = make_float4(0.f, 0.f, 0.f, 0.f);
            if (nn < N_NODES) {
                int zr = z[nn];
                v = ((const float4*)(emb + (size_t)zr * HID))[lane];
            }
            ((float4*)xw)[lane + 32 * j] = v;
            ((float4*)(g_h + (size_t)nn * HID))[lane] = v;
            ((float4*)(g_agg + (size_t)nn * HID))[lane] = make_float4(0.f, 0.f, 0.f, 0.f);
        }
        __syncwarp();
        float a[4][4];
        #pragma unroll
        for (int r = 0; r < 4; r++) { a[r][0] = a[r][1] = a[r][2] = a[r][3] = 0.f; }
        #pragma unroll 4
        for (int k = 0; k < HID; k++) {
            float4 w = *(const float4*)(Ws + k * HID + c0);
            #pragma unroll
            for (int r = 0; r < 4; r++) {
                float v = xw[r * HID + k];
                a[r][0] += v * w.x; a[r][1] += v * w.y; a[r][2] += v * w.z; a[r][3] += v * w.w;
            }
        }
        #pragma unroll
        for (int r = 0; r < 4; r++)
            *(float4*)(g_xh + (size_t)(n0 + r) * HID + c0) =
                make_float4(a[r][0], a[r][1], a[r][2], a[r][3]);
        __syncwarp();
    }
}

// ---------------- edge filter MLP (unchanged from R6) ----------------
__global__ void __launch_bounds__(256, 2)
edge_mma_kernel(const int* __restrict__ ei,
                const float* __restrict__ w1, const float* __restrict__ b1,
                const float* __restrict__ w2, const float* __restrict__ b2) {
    extern __shared__ char smem[];
    half* w1h = (half*)(smem + OFF_W1h);
    half* w2h = (half*)(smem + OFF_W2h);
    half* Ah  = (half*)(smem + OFF_A);
    half* Hh  = (half*)(smem + OFF_H);
    float* b1s = (float*)(smem + OFF_B1);
    float* b2s = (float*)(smem + OFF_B2);

    const int tid = threadIdx.x, wid = tid >> 5, lane = tid & 31;
    const int g = lane >> 2, tg = lane & 3;
    const int rt = wid & 3, nh = wid >> 2;
    const int aedge = tid >> 1, aseg = tid & 1;

    for (int i = tid; i < 128 * 64; i += 256) {
        int n = i >> 6, k = i & 63;
        w1h[n * SA1 + k] = __float2half_rn((k < NF) ? w1[k * HID + n] : 0.f);
    }
    for (int i = tid; i < 128 * 128; i += 256) {
        int n = i >> 7, k = i & 127;
        w2h[n * SA2 + k] = __float2half_rn(w2[k * HID + n]);
    }
    if (tid < HID) { b1s[tid] = b1[tid]; b2s[tid] = b2[tid]; }

    const uint32_t aU  = smem_to_u32(Ah);
    const uint32_t hU  = smem_to_u32(Hh);
    const uint32_t w1U = smem_to_u32(w1h);
    const uint32_t w2U = smem_to_u32(w2h);
    const int lrow = lane & 15;
    const int lkh  = (lane >> 4) << 3;

    uint4* aDst = (uint4*)(Ah + aedge * SA1 + aseg * 32);
    {
        const uint4* src = (const uint4*)(g_feat + ((size_t)blockIdx.x * 128 + aedge) * 64 + aseg * 32);
        #pragma unroll
        for (int j = 0; j < 4; j++) aDst[j] = src[j];
    }
    __syncthreads();

    for (int t = blockIdx.x; t < EDGE_TILES; t += gridDim.x) {
        const int e0 = t * 128;
        int rA[2], rB[2], cA[2], cB[2];
        float CA[2], CB[2];
        {
            int base = e0 + rt * 32 + g;
            #pragma unroll
            for (int mt = 0; mt < 2; mt++) {
                int ea = base + mt * 16, eb = ea + 8;
                rA[mt] = ei[ea];            rB[mt] = ei[eb];
                cA[mt] = ei[N_EDGES + ea];  cB[mt] = ei[N_EDGES + eb];
                CA[mt] = g_Cc[ea];          CB[mt] = g_Cc[eb];
            }
        }

        float acc[2][8][4];
        #pragma unroll
        for (int mt = 0; mt < 2; mt++)
            #pragma unroll
            for (int j = 0; j < 8; j++)
                #pragma unroll
                for (int q = 0; q < 4; q++) acc[mt][j][q] = 0.f;

        #pragma unroll
        for (int ks = 0; ks < 4; ks++) {
            const int k0 = ks * 16;
            uint32_t am[2][4];
            #pragma unroll
            for (int mt = 0; mt < 2; mt++) {
                uint32_t addr = aU + (uint32_t)(((rt * 32 + mt * 16 + lrow) * SA1 + k0 + lkh) << 1);
                ldm_x4(am[mt][0], am[mt][1], am[mt][2], am[mt][3], addr);
            }
            #pragma unroll
            for (int jj = 0; jj < 4; jj++) {
                uint32_t b0, b1r, b2r, b3;
                uint32_t addr = w1U + (uint32_t)(((nh * 64 + jj * 16 + lrow) * SA1 + k0 + lkh) << 1);
                ldm_x4(b0, b1r, b2r, b3, addr);
                #pragma unroll
                for (int mt = 0; mt < 2; mt++) {
                    mma16816(acc[mt][2 * jj],     am[mt][0], am[mt][1], am[mt][2], am[mt][3], b0,  b2r);
                    mma16816(acc[mt][2 * jj + 1], am[mt][0], am[mt][1], am[mt][2], am[mt][3], b1r, b3);
                }
            }
        }
        __syncthreads();

        #pragma unroll
        for (int mt = 0; mt < 2; mt++) {
            int r0 = rt * 32 + mt * 16 + g;
            #pragma unroll
            for (int j = 0; j < 8; j++) {
                int c = nh * 64 + j * 8 + tg * 2;
                float bx = b1s[c], by = b1s[c + 1];
                *(half2*)(Hh + (size_t)r0 * SA2 + c) =
                    __floats2half2_rn(sspf(acc[mt][j][0] + bx), sspf(acc[mt][j][1] + by));
                *(half2*)(Hh + (size_t)(r0 + 8) * SA2 + c) =
                    __floats2half2_rn(sspf(acc[mt][j][2] + bx), sspf(acc[mt][j][3] + by));
            }
        }

        uint4 ap[4];
        const int tn = t + gridDim.x;
        if (tn < EDGE_TILES) {
            const uint4* src = (const uint4*)(g_feat + ((size_t)tn * 128 + aedge) * 64 + aseg * 32);
            #pragma unroll
            for (int j = 0; j < 4; j++) ap[j] = src[j];
        }
        __syncthreads();

        #pragma unroll
        for (int mt = 0; mt < 2; mt++)
            #pragma unroll
            for (int j = 0; j < 8; j++)
                #pragma unroll
                for (int q = 0; q < 4; q++) acc[mt][j][q] = 0.f;
        #pragma unroll
        for (int ks = 0; ks < 8; ks++) {
            const int k0 = ks * 16;
            uint32_t am[2][4];
            #pragma unroll
            for (int mt = 0; mt < 2; mt++) {
                uint32_t addr = hU + (uint32_t)(((rt * 32 + mt * 16 + lrow) * SA2 + k0 + lkh) << 1);
                ldm_x4(am[mt][0], am[mt][1], am[mt][2], am[mt][3], addr);
            }
            #pragma unroll
            for (int jj = 0; jj < 4; jj++) {
                uint32_t b0, b1r, b2r, b3;
                uint32_t addr = w2U + (uint32_t)(((nh * 64 + jj * 16 + lrow) * SA2 + k0 + lkh) << 1);
                ldm_x4(b0, b1r, b2r, b3, addr);
                #pragma unroll
                for (int mt = 0; mt < 2; mt++) {
                    mma16816(acc[mt][2 * jj],     am[mt][0], am[mt][1], am[mt][2], am[mt][3], b0,  b2r);
                    mma16816(acc[mt][2 * jj + 1], am[mt][0], am[mt][1], am[mt][2], am[mt][3], b1r, b3);
                }
            }
        }

        if (tn < EDGE_TILES) {
            #pragma unroll
            for (int j = 0; j < 4; j++) aDst[j] = ap[j];
        }

        #pragma unroll
        for (int mt = 0; mt < 2; mt++) {
            const float* xA = g_xh + (size_t)rA[mt] * HID;
            const float* xB = g_xh + (size_t)rB[mt] * HID;
            float2 va[8], vb[8];
            #pragma unroll
            for (int j = 0; j < 8; j++) {
                int c = nh * 64 + j * 8 + tg * 2;
                va[j] = *(const float2*)(xA + c);
                vb[j] = *(const float2*)(xB + c);
            }
            float* aA = g_agg + (size_t)cA[mt] * HID;
            float* aB = g_agg + (size_t)cB[mt] * HID;
            float Ca = CA[mt], Cb = CB[mt];
            #pragma unroll
            for (int j = 0; j < 8; j++) {
                int c = nh * 64 + j * 8 + tg * 2;
                float bx = b2s[c], by = b2s[c + 1];
                float p0 = (acc[mt][j][0] + bx) * Ca * va[j].x;
                float p1 = (acc[mt][j][1] + by) * Ca * va[j].y;
                asm volatile("red.global.add.v2.f32 [%0], {%1, %2};"
                             :: "l"(aA + c), "f"(p0), "f"(p1) : "memory");
                float q0 = (acc[mt][j][2] + bx) * Cb * vb[j].x;
                float q1 = (acc[mt][j][3] + by) * Cb * vb[j].y;
                asm volatile("red.global.add.v2.f32 [%0], {%1, %2};"
                             :: "l"(aB + c), "f"(q0), "f"(q1) : "memory");
            }
        }
        __syncthreads();
    }
}

// ---------------- node phase via fp16 mma ----------------
// GEMM1: D1 = agg @ cf2; t = ssp(D1+bA)
// GEMM2: D2 = t @ lin;   hn = g_h + D2 + bB  (residual; store g_h unless LAST)
// GEMM3: !LAST: g_xh = hn @ cf1_next
//        LAST : rowsum(ssp(hn@o1 + o1b) * o2) + o2b -> atomicAdd(out[batch])
template <int LAST>
__global__ void __launch_bounds__(256, 1)
node_mma(const float* __restrict__ wA, const float* __restrict__ bA,
         const float* __restrict__ wB, const float* __restrict__ bB,
         const float* __restrict__ wC,
         const float* __restrict__ o1b, const float* __restrict__ o2w,
         const float* __restrict__ o2b,
         const int* __restrict__ batch, float* __restrict__ out) {
    extern __shared__ char smem[];
    half* WAh = (half*)(smem + NM_WA);
    half* WBh = (half*)(smem + NM_WB);
    half* WCh = (half*)(smem + NM_WC);
    half* Ah  = (half*)(smem + NM_AT);
    half* Hh  = (half*)(smem + NM_HT);
    float* bAs = (float*)(smem + NM_BA);
    float* bBs = (float*)(smem + NM_BB);
    float* BOs = (float*)(smem + NM_BO);
    float* O2s = (float*)(smem + NM_O2);

    const int tid = threadIdx.x, wid = tid >> 5, lane = tid & 31;
    const int g = lane >> 2, tg = lane & 3;
    const int rt = wid & 3, nh = wid >> 2;

    for (int i = tid; i < 128 * 128; i += 256) {
        int n = i >> 7, k = i & 127;
        WAh[n * SA2 + k] = __float2half_rn(wA[k * HID + n]);
        WBh[n * SA2 + k] = __float2half_rn(wB[k * HID + n]);
    }
    if (LAST) {
        for (int i = tid; i < 64 * 128; i += 256) {
            int n = i >> 7, k = i & 127;
            WCh[n * SA2 + k] = __float2half_rn(wC[k * 64 + n]);
        }
        if (tid < 64) { BOs[tid] = o1b[tid]; O2s[tid] = o2w[tid]; }
    } else {
        for (int i = tid; i < 128 * 128; i += 256) {
            int n = i >> 7, k = i & 127;
            WCh[n * SA2 + k] = __float2half_rn(wC[k * HID + n]);
        }
    }
    if (tid < HID) { bAs[tid] = bA[tid]; bBs[tid] = bB[tid]; }

    const uint32_t aU  = smem_to_u32(Ah);
    const uint32_t hU  = smem_to_u32(Hh);
    const uint32_t wAU = smem_to_u32(WAh);
    const uint32_t wBU = smem_to_u32(WBh);
    const uint32_t wCU = smem_to_u32(WCh);
    const int lrow = lane & 15;
    const int lkh  = (lane >> 4) << 3;
    const float ob = LAST ? o2b[0] : 0.f;

    for (int t = blockIdx.x; t < NT_TILES; t += gridDim.x) {
        const int n0 = t * 128;
        // ---- load A = fp16(agg rows), zero agg ----
        for (int i = tid; i < 128 * 32; i += 256) {
            int row = i >> 5, c4 = i & 31;
            float4* ap = (float4*)(g_agg + (size_t)(n0 + row) * HID) + c4;
            float4 v = *ap;
            *ap = make_float4(0.f, 0.f, 0.f, 0.f);
            half2 h0 = __floats2half2_rn(v.x, v.y);
            half2 h1 = __floats2half2_rn(v.z, v.w);
            *(uint2*)(Ah + (size_t)row * SA2 + c4 * 4) =
                make_uint2(*(uint32_t*)&h0, *(uint32_t*)&h1);
        }
        __syncthreads();   // s0: A ready (and prev-iter G3 done)

        float acc[2][8][4];
        // ---- GEMM1: A @ WA ----
        #pragma unroll
        for (int mt = 0; mt < 2; mt++)
            #pragma unroll
            for (int j = 0; j < 8; j++)
                #pragma unroll
                for (int q = 0; q < 4; q++) acc[mt][j][q] = 0.f;
        #pragma unroll
        for (int ks = 0; ks < 8; ks++) {
            const int k0 = ks * 16;
            uint32_t am[2][4];
            #pragma unroll
            for (int mt = 0; mt < 2; mt++) {
                uint32_t addr = aU + (uint32_t)(((rt * 32 + mt * 16 + lrow) * SA2 + k0 + lkh) << 1);
                ldm_x4(am[mt][0], am[mt][1], am[mt][2], am[mt][3], addr);
            }
            #pragma unroll
            for (int jj = 0; jj < 4; jj++) {
                uint32_t b0, b1r, b2r, b3;
                uint32_t addr = wAU + (uint32_t)(((nh * 64 + jj * 16 + lrow) * SA2 + k0 + lkh) << 1);
                ldm_x4(b0, b1r, b2r, b3, addr);
                #pragma unroll
                for (int mt = 0; mt < 2; mt++) {
                    mma16816(acc[mt][2 * jj],     am[mt][0], am[mt][1], am[mt][2], am[mt][3], b0,  b2r);
                    mma16816(acc[mt][2 * jj + 1], am[mt][0], am[mt][1], am[mt][2], am[mt][3], b1r, b3);
                }
            }
        }
        // epi1: H = fp16(ssp(D1 + bA))
        #pragma unroll
        for (int mt = 0; mt < 2; mt++) {
            int r0 = rt * 32 + mt * 16 + g;
            #pragma unroll
            for (int j = 0; j < 8; j++) {
                int c = nh * 64 + j * 8 + tg * 2;
                float bx = bAs[c], by = bAs[c + 1];
                *(half2*)(Hh + (size_t)r0 * SA2 + c) =
                    __floats2half2_rn(sspf(acc[mt][j][0] + bx), sspf(acc[mt][j][1] + by));
                *(half2*)(Hh + (size_t)(r0 + 8) * SA2 + c) =
                    __floats2half2_rn(sspf(acc[mt][j][2] + bx), sspf(acc[mt][j][3] + by));
            }
        }
        __syncthreads();   // s1: H ready, A free

        // ---- GEMM2: H @ WB ----
        #pragma unroll
        for (int mt = 0; mt < 2; mt++)
            #pragma unroll
            for (int j = 0; j < 8; j++)
                #pragma unroll
                for (int q = 0; q < 4; q++) acc[mt][j][q] = 0.f;
        #pragma unroll
        for (int ks = 0; ks < 8; ks++) {
            const int k0 = ks * 16;
            uint32_t am[2][4];
            #pragma unroll
            for (int mt = 0; mt < 2; mt++) {
                uint32_t addr = hU + (uint32_t)(((rt * 32 + mt * 16 + lrow) * SA2 + k0 + lkh) << 1);
                ldm_x4(am[mt][0], am[mt][1], am[mt][2], am[mt][3], addr);
            }
            #pragma unroll
            for (int jj = 0; jj < 4; jj++) {
                uint32_t b0, b1r, b2r, b3;
                uint32_t addr = wBU + (uint32_t)(((nh * 64 + jj * 16 + lrow) * SA2 + k0 + lkh) << 1);
                ldm_x4(b0, b1r, b2r, b3, addr);
                #pragma unroll
                for (int mt = 0; mt < 2; mt++) {
                    mma16816(acc[mt][2 * jj],     am[mt][0], am[mt][1], am[mt][2], am[mt][3], b0,  b2r);
                    mma16816(acc[mt][2 * jj + 1], am[mt][0], am[mt][1], am[mt][2], am[mt][3], b1r, b3);
                }
            }
        }
        // epi2: hn = h + D2 + bB; store g_h (!LAST); A' = fp16(hn)
        #pragma unroll
        for (int mt = 0; mt < 2; mt++) {
            int r0 = rt * 32 + mt * 16 + g;
            int gr0 = n0 + r0;
            #pragma unroll
            for (int j = 0; j < 8; j++) {
                int c = nh * 64 + j * 8 + tg * 2;
                float bx = bBs[c], by = bBs[c + 1];
                float2 h0 = *(const float2*)(g_h + (size_t)gr0 * HID + c);
                float2 h1 = *(const float2*)(g_h + (size_t)(gr0 + 8) * HID + c);
                float n00 = acc[mt][j][0] + bx + h0.x;
                float n01 = acc[mt][j][1] + by + h0.y;
                float n10 = acc[mt][j][2] + bx + h1.x;
                float n11 = acc[mt][j][3] + by + h1.y;
                if (!LAST) {
                    *(float2*)(g_h + (size_t)gr0 * HID + c)       = make_float2(n00, n01);
                    *(float2*)(g_h + (size_t)(gr0 + 8) * HID + c) = make_float2(n10, n11);
                }
                *(half2*)(Ah + (size_t)r0 * SA2 + c)       = __floats2half2_rn(n00, n01);
                *(half2*)(Ah + (size_t)(r0 + 8) * SA2 + c) = __floats2half2_rn(n10, n11);
            }
        }
        __syncthreads();   // s2: A' ready, H free

        // ---- GEMM3: A' @ WC ----
        const int NJ3 = LAST ? 2 : 4;
        #pragma unroll
        for (int mt = 0; mt < 2; mt++)
            #pragma unroll
            for (int j = 0; j < 8; j++)
                #pragma unroll
                for (int q = 0; q < 4; q++) acc[mt][j][q] = 0.f;
        #pragma unroll
        for (int ks = 0; ks < 8; ks++) {
            const int k0 = ks * 16;
            uint32_t am[2][4];
            #pragma unroll
            for (int mt = 0; mt < 2; mt++) {
                uint32_t addr = aU + (uint32_t)(((rt * 32 + mt * 16 + lrow) * SA2 + k0 + lkh) << 1);
                ldm_x4(am[mt][0], am[mt][1], am[mt][2], am[mt][3], addr);
            }
            #pragma unroll
            for (int jj = 0; jj < 4; jj++) {
                if (jj >= NJ3) break;
                uint32_t b0, b1r, b2r, b3;
                int ncol = LAST ? (nh * 32 + jj * 16) : (nh * 64 + jj * 16);
                uint32_t addr = wCU + (uint32_t)(((ncol + lrow) * SA2 + k0 + lkh) << 1);
                ldm_x4(b0, b1r, b2r, b3, addr);
                #pragma unroll
                for (int mt = 0; mt < 2; mt++) {
                    mma16816(acc[mt][2 * jj],     am[mt][0], am[mt][1], am[mt][2], am[mt][3], b0,  b2r);
                    mma16816(acc[mt][2 * jj + 1], am[mt][0], am[mt][1], am[mt][2], am[mt][3], b1r, b3);
                }
            }
        }
        // epi3
        if (!LAST) {
            #pragma unroll
            for (int mt = 0; mt < 2; mt++) {
                int gr0 = n0 + rt * 32 + mt * 16 + g;
                #pragma unroll
                for (int j = 0; j < 8; j++) {
                    int c = nh * 64 + j * 8 + tg * 2;
                    *(float2*)(g_xh + (size_t)gr0 * HID + c) =
                        make_float2(acc[mt][j][0], acc[mt][j][1]);
                    *(float2*)(g_xh + (size_t)(gr0 + 8) * HID + c) =
                        make_float2(acc[mt][j][2], acc[mt][j][3]);
                }
            }
        } else {
            #pragma unroll
            for (int mt = 0; mt < 2; mt++) {
                float s0 = 0.f, s1 = 0.f;
                #pragma unroll
                for (int j = 0; j < 4; j++) {
                    int c = nh * 32 + j * 8 + tg * 2;
                    float bx = BOs[c], by = BOs[c + 1];
                    float wx = O2s[c], wy = O2s[c + 1];
                    s0 += sspf(acc[mt][j][0] + bx) * wx + sspf(acc[mt][j][1] + by) * wy;
                    s1 += sspf(acc[mt][j][2] + bx) * wx + sspf(acc[mt][j][3] + by) * wy;
                }
                s0 += __shfl_xor_sync(0xffffffffu, s0, 1);
                s0 += __shfl_xor_sync(0xffffffffu, s0, 2);
                s1 += __shfl_xor_sync(0xffffffffu, s1, 1);
                s1 += __shfl_xor_sync(0xffffffffu, s1, 2);
                if (tg == 0) {
                    int rowA = n0 + rt * 32 + mt * 16 + g;
                    int rowB = rowA + 8;
                    float add = (nh == 0) ? ob : 0.f;
                    if (rowA < N_NODES) atomicAdd(&out[batch[rowA]], s0 + add);
                    if (rowB < N_NODES) atomicAdd(&out[batch[rowB]], s1 + add);
                }
            }
        }
        __syncthreads();   // s3: A' free before next tile's A load
    }
}

// ---------------- launch ----------------
extern "C" void kernel_launch(void* const* d_in, const int* in_sizes, int n_in,
                              void* d_out, int out_size) {
    const int*   z      = (const int*)  d_in[0];
    const float* pos    = (const float*)d_in[1];
    const int*   batch  = (const int*)  d_in[2];
    const int*   ei     = (const int*)  d_in[3];
    const float* eattr  = (const float*)d_in[4];
    const float* emb    = (const float*)d_in[5];
    const float* mlp_w1 = (const float*)d_in[6];
    const float* mlp_b1 = (const float*)d_in[7];
    const float* mlp_w2 = (const float*)d_in[8];
    const float* mlp_b2 = (const float*)d_in[9];
    const float* cf1_w  = (const float*)d_in[10];
    const float* cf2_w  = (const float*)d_in[11];
    const float* cf2_b  = (const float*)d_in[12];
    const float* lin_w  = (const float*)d_in[13];
    const float* lin_b  = (const float*)d_in[14];
    const float* o1w    = (const float*)d_in[15];
    const float* o1b    = (const float*)d_in[16];
    const float* o2w    = (const float*)d_in[17];
    const float* o2b    = (const float*)d_in[18];
    float* out = (float*)d_out;

    const int NI_SMEM = (HID * HID + 8 * 512) * (int)sizeof(float);
    cudaFuncSetAttribute(edge_mma_kernel, cudaFuncAttributeMaxDynamicSharedMemorySize, EK_SMEM);
    cudaFuncSetAttribute(node_init,   cudaFuncAttributeMaxDynamicSharedMemorySize, NI_SMEM);
    cudaFuncSetAttribute(node_mma<0>, cudaFuncAttributeMaxDynamicSharedMemorySize, NM_SMEM);
    cudaFuncSetAttribute(node_mma<1>, cudaFuncAttributeMaxDynamicSharedMemorySize, NM_SMEM);

    zero_out_kernel<<<1, 32>>>(out);
    edge_pre_kernel<<<(2 * N_EDGES + 255) / 256, 256>>>(ei, pos, eattr);
    node_init<<<296, 256, NI_SMEM>>>(z, emb, cf1_w);

    for (int l = 0; l < 3; l++) {
        edge_mma_kernel<<<296, 256, EK_SMEM>>>(ei,
                                               mlp_w1 + (size_t)l * NF * HID, mlp_b1 + (size_t)l * HID,
                                               mlp_w2 + (size_t)l * HID * HID, mlp_b2 + (size_t)l * HID);
        if (l < 2) {
            node_mma<0><<<148, 256, NM_SMEM>>>(
                cf2_w + (size_t)l * HID * HID, cf2_b + (size_t)l * HID,
                lin_w + (size_t)l * HID * HID, lin_b + (size_t)l * HID,
                cf1_w + (size_t)(l + 1) * HID * HID,
                nullptr, nullptr, nullptr, batch, out);
        } else {
            node_mma<1><<<148, 256, NM_SMEM>>>(
                cf2_w + (size_t)l * HID * HID, cf2_b + (size_t)l * HID,
                lin_w + (size_t)l * HID * HID, lin_b + (size_t)l * HID,
                o1w, o1b, o2w, o2b, batch, out);
        }
    }
}

// round 8
// speedup vs baseline: 6.3368x; 1.0715x over previous
#include <cuda_runtime.h>
#include <cuda_fp16.h>
#include <cstdint>
#include <math.h>

#define N_NODES 20000
#define N_PAD   20096            // 157 * 128
#define NT_TILES 157
#define N_EDGES 640000
#define HID 128
#define NB 3
#define NGS 47
#define NF 50
#define B_GRAPHS 16
#define LOG2F_ 0.69314718055994530942f
#define CUTF 10.0f
#define PI_F 3.14159265358979323846f
#define EDGE_TILES (N_EDGES / 128)   // 5000

#define SA1 72     // halves stride for A / W1 tiles (K=64 + 8 pad)
#define SA2 136    // halves stride for K=128 tiles (+8 pad)
#define SW  136    // float stride for staged W tile (64 rows)

// ---- edge kernel smem byte offsets ----
#define OFF_W1h 0                         // 128*72*2  = 18432
#define OFF_W2h 18432                     // 128*136*2 = 34816
#define OFF_A   53248                     // 18432
#define OFF_H   71680                     // 34816  (also W staging: 64*136*4)
#define OFF_B1  106496                    // 512
#define OFF_B2  107008                    // 512
#define EK_SMEM 107520                    // 2 CTAs/SM

// ---- node kernel smem byte offsets ----
#define NM_WA  0
#define NM_WB  34816
#define NM_WC  69632
#define NM_AT  104448
#define NM_HT  139264
#define NM_BA  174080
#define NM_BB  174592
#define NM_BO  175104
#define NM_O2  175360
#define NM_SMEM 175616

// ---------------- scratch ----------------
__device__ float g_h  [N_PAD * HID];
__device__ float g_xh [N_PAD * HID];
__device__ float g_agg[N_PAD * HID];
__device__ float g_Cc [N_EDGES];
__device__ half  g_feat[(size_t)N_EDGES * 64];

__device__ __forceinline__ float sspf(float x) {
    float e = __expf(-fabsf(x));
    return fmaxf(x, 0.f) + __logf(1.f + e) - LOG2F_;
}
__device__ __forceinline__ uint32_t smem_to_u32(const void* p) {
    uint32_t a;
    asm("{ .reg .u64 t; cvta.to.shared.u64 t, %1; cvt.u32.u64 %0, t; }" : "=r"(a) : "l"(p));
    return a;
}
__device__ __forceinline__ void ldm_x4(uint32_t& r0, uint32_t& r1, uint32_t& r2, uint32_t& r3, uint32_t a) {
    asm volatile("ldmatrix.sync.aligned.m8n8.x4.shared.b16 {%0,%1,%2,%3}, [%4];"
                 : "=r"(r0), "=r"(r1), "=r"(r2), "=r"(r3) : "r"(a));
}
__device__ __forceinline__ void mma16816(float* c, uint32_t a0, uint32_t a1, uint32_t a2, uint32_t a3,
                                         uint32_t b0, uint32_t b1) {
    asm volatile("mma.sync.aligned.m16n8k16.row.col.f32.f16.f16.f32 "
                 "{%0,%1,%2,%3}, {%4,%5,%6,%7}, {%8,%9}, {%0,%1,%2,%3};"
                 : "+f"(c[0]), "+f"(c[1]), "+f"(c[2]), "+f"(c[3])
                 : "r"(a0), "r"(a1), "r"(a2), "r"(a3), "r"(b0), "r"(b1));
}

// ---------------- small kernels ----------------
__global__ void zero_out_kernel(float* out) {
    if (threadIdx.x < B_GRAPHS) out[threadIdx.x] = 0.f;
}

__global__ void edge_pre_kernel(const int* __restrict__ ei, const float* __restrict__ pos,
                                const float* __restrict__ eattr) {
    int t = blockIdx.x * blockDim.x + threadIdx.x;
    int e = t >> 1, seg = t & 1;
    if (e >= N_EDGES) return;
    int r = ei[e], c = ei[N_EDGES + e];
    float dx = pos[r * 3 + 0] - pos[c * 3 + 0];
    float dy = pos[r * 3 + 1] - pos[c * 3 + 1];
    float dz = pos[r * 3 + 2] - pos[c * 3 + 2];
    float ew = sqrtf(dx * dx + dy * dy + dz * dz);
    const float step = CUTF / (float)(NGS - 1);
    const float coeff = -0.5f / (step * step);

    float f[32];
    if (seg == 0) {
        g_Cc[e] = 0.5f * (cosf(ew * (PI_F / CUTF)) + 1.f);
        f[0] = eattr[e * NB + 0];
        f[1] = eattr[e * NB + 1];
        f[2] = eattr[e * NB + 2];
        #pragma unroll
        for (int j = 3; j < 32; j++) {
            float d = ew - (float)(j - 3) * step;
            f[j] = __expf(coeff * d * d);
        }
    } else {
        #pragma unroll
        for (int j = 0; j < 18; j++) {
            float d = ew - (float)(29 + j) * step;
            f[j] = __expf(coeff * d * d);
        }
        #pragma unroll
        for (int j = 18; j < 32; j++) f[j] = 0.f;
    }
    half2 tmp[16];
    #pragma unroll
    for (int j = 0; j < 16; j++) tmp[j] = __floats2half2_rn(f[2 * j], f[2 * j + 1]);
    uint4* dst = (uint4*)(g_feat + (size_t)e * 64 + seg * 32);
    #pragma unroll
    for (int j = 0; j < 4; j++) dst[j] = ((uint4*)tmp)[j];
}

// ---------------- node_init ----------------
__global__ void __launch_bounds__(256)
node_init(const int* __restrict__ z, const float* __restrict__ emb,
          const float* __restrict__ W) {
    extern __shared__ float sm[];
    float* Ws = sm;
    float* xs = Ws + HID * HID;
    for (int i = threadIdx.x; i < HID * HID; i += blockDim.x) Ws[i] = W[i];
    __syncthreads();

    const int wid = threadIdx.x >> 5, lane = threadIdx.x & 31;
    float* xw = xs + wid * 512;
    const int gw = blockIdx.x * 8 + wid, nw = gridDim.x * 8;
    const int c0 = lane * 4;

    for (int gidx = gw; gidx < N_PAD / 4; gidx += nw) {
        int n0 = gidx * 4;
        #pragma unroll
        for (int j = 0; j < 4; j++) {
            int nn = n0 + j;
            float4 v = make_float4(0.f, 0.f, 0.f, 0.f);
            if (nn < N_NODES) {
                int zr = z[nn];
                v = ((const float4*)(emb + (size_t)zr * HID))[lane];
            }
            ((float4*)xw)[lane + 32 * j] = v;
            ((float4*)(g_h + (size_t)nn * HID))[lane] = v;
            ((float4*)(g_agg + (size_t)nn * HID))[lane] = make_float4(0.f, 0.f, 0.f, 0.f);
        }
        __syncwarp();
        float a[4][4];
        #pragma unroll
        for (int r = 0; r < 4; r++) { a[r][0] = a[r][1] = a[r][2] = a[r][3] = 0.f; }
        #pragma unroll 4
        for (int k = 0; k < HID; k++) {
            float4 w = *(const float4*)(Ws + k * HID + c0);
            #pragma unroll
            for (int r = 0; r < 4; r++) {
                float v = xw[r * HID + k];
                a[r][0] += v * w.x; a[r][1] += v * w.y; a[r][2] += v * w.z; a[r][3] += v * w.w;
            }
        }
        #pragma unroll
        for (int r = 0; r < 4; r++)
            *(float4*)(g_xh + (size_t)(n0 + r) * HID + c0) =
                make_float4(a[r][0], a[r][1], a[r][2], a[r][3]);
        __syncwarp();
    }
}

// ---------------- edge filter MLP ----------------
__global__ void __launch_bounds__(256, 2)
edge_mma_kernel(const int* __restrict__ ei,
                const float* __restrict__ w1, const float* __restrict__ b1,
                const float* __restrict__ w2, const float* __restrict__ b2) {
    extern __shared__ char smem[];
    half* w1h = (half*)(smem + OFF_W1h);
    half* w2h = (half*)(smem + OFF_W2h);
    half* Ah  = (half*)(smem + OFF_A);
    half* Hh  = (half*)(smem + OFF_H);
    float* Wst = (float*)(smem + OFF_H);     // W staging aliases H
    float* b1s = (float*)(smem + OFF_B1);
    float* b2s = (float*)(smem + OFF_B2);

    const int tid = threadIdx.x, wid = tid >> 5, lane = tid & 31;
    const int g = lane >> 2, tg = lane & 3;
    const int rt = wid & 3, nh = wid >> 2;
    const int aedge = tid >> 1, aseg = tid & 1;

    for (int i = tid; i < 128 * 64; i += 256) {
        int n = i >> 6, k = i & 63;
        w1h[n * SA1 + k] = __float2half_rn((k < NF) ? w1[k * HID + n] : 0.f);
    }
    for (int i = tid; i < 128 * 128; i += 256) {
        int n = i >> 7, k = i & 127;
        w2h[n * SA2 + k] = __float2half_rn(w2[k * HID + n]);
    }
    if (tid < HID) { b1s[tid] = b1[tid]; b2s[tid] = b2[tid]; }

    const uint32_t aU  = smem_to_u32(Ah);
    const uint32_t hU  = smem_to_u32(Hh);
    const uint32_t w1U = smem_to_u32(w1h);
    const uint32_t w2U = smem_to_u32(w2h);
    const int lrow = lane & 15;
    const int lkh  = (lane >> 4) << 3;

    uint4* aDst = (uint4*)(Ah + aedge * SA1 + aseg * 32);
    {
        const uint4* src = (const uint4*)(g_feat + ((size_t)blockIdx.x * 128 + aedge) * 64 + aseg * 32);
        #pragma unroll
        for (int j = 0; j < 4; j++) aDst[j] = src[j];
    }
    __syncthreads();

    for (int t = blockIdx.x; t < EDGE_TILES; t += gridDim.x) {
        const int e0 = t * 128;
        float acc[2][8][4];
        #pragma unroll
        for (int mt = 0; mt < 2; mt++)
            #pragma unroll
            for (int j = 0; j < 8; j++)
                #pragma unroll
                for (int q = 0; q < 4; q++) acc[mt][j][q] = 0.f;

        // ---- GEMM1 ----
        #pragma unroll
        for (int ks = 0; ks < 4; ks++) {
            const int k0 = ks * 16;
            uint32_t am[2][4];
            #pragma unroll
            for (int mt = 0; mt < 2; mt++) {
                uint32_t addr = aU + (uint32_t)(((rt * 32 + mt * 16 + lrow) * SA1 + k0 + lkh) << 1);
                ldm_x4(am[mt][0], am[mt][1], am[mt][2], am[mt][3], addr);
            }
            #pragma unroll
            for (int jj = 0; jj < 4; jj++) {
                uint32_t b0, b1r, b2r, b3;
                uint32_t addr = w1U + (uint32_t)(((nh * 64 + jj * 16 + lrow) * SA1 + k0 + lkh) << 1);
                ldm_x4(b0, b1r, b2r, b3, addr);
                #pragma unroll
                for (int mt = 0; mt < 2; mt++) {
                    mma16816(acc[mt][2 * jj],     am[mt][0], am[mt][1], am[mt][2], am[mt][3], b0,  b2r);
                    mma16816(acc[mt][2 * jj + 1], am[mt][0], am[mt][1], am[mt][2], am[mt][3], b1r, b3);
                }
            }
        }
        __syncthreads();   // A consumed; H/Wst from prev iter consumed

        // ---- epilogue1: H = fp16(ssp(D1 + b1)) ----
        #pragma unroll
        for (int mt = 0; mt < 2; mt++) {
            int r0 = rt * 32 + mt * 16 + g;
            #pragma unroll
            for (int j = 0; j < 8; j++) {
                int c = nh * 64 + j * 8 + tg * 2;
                float bx = b1s[c], by = b1s[c + 1];
                *(half2*)(Hh + (size_t)r0 * SA2 + c) =
                    __floats2half2_rn(sspf(acc[mt][j][0] + bx), sspf(acc[mt][j][1] + by));
                *(half2*)(Hh + (size_t)(r0 + 8) * SA2 + c) =
                    __floats2half2_rn(sspf(acc[mt][j][2] + bx), sspf(acc[mt][j][3] + by));
            }
        }

        // prefetch next A tile into regs
        uint4 ap[4];
        const int tn = t + gridDim.x;
        if (tn < EDGE_TILES) {
            const uint4* src = (const uint4*)(g_feat + ((size_t)tn * 128 + aedge) * 64 + aseg * 32);
            #pragma unroll
            for (int j = 0; j < 4; j++) ap[j] = src[j];
        }
        __syncthreads();   // H ready

        // ---- GEMM2 ----
        #pragma unroll
        for (int mt = 0; mt < 2; mt++)
            #pragma unroll
            for (int j = 0; j < 8; j++)
                #pragma unroll
                for (int q = 0; q < 4; q++) acc[mt][j][q] = 0.f;
        #pragma unroll
        for (int ks = 0; ks < 8; ks++) {
            const int k0 = ks * 16;
            uint32_t am[2][4];
            #pragma unroll
            for (int mt = 0; mt < 2; mt++) {
                uint32_t addr = hU + (uint32_t)(((rt * 32 + mt * 16 + lrow) * SA2 + k0 + lkh) << 1);
                ldm_x4(am[mt][0], am[mt][1], am[mt][2], am[mt][3], addr);
            }
            #pragma unroll
            for (int jj = 0; jj < 4; jj++) {
                uint32_t b0, b1r, b2r, b3;
                uint32_t addr = w2U + (uint32_t)(((nh * 64 + jj * 16 + lrow) * SA2 + k0 + lkh) << 1);
                ldm_x4(b0, b1r, b2r, b3, addr);
                #pragma unroll
                for (int mt = 0; mt < 2; mt++) {
                    mma16816(acc[mt][2 * jj],     am[mt][0], am[mt][1], am[mt][2], am[mt][3], b0,  b2r);
                    mma16816(acc[mt][2 * jj + 1], am[mt][0], am[mt][1], am[mt][2], am[mt][3], b1r, b3);
                }
            }
        }

        // store next A tile (A free since GEMM1-end sync)
        if (tn < EDGE_TILES) {
            #pragma unroll
            for (int j = 0; j < 4; j++) aDst[j] = ap[j];
        }
        __syncthreads();   // all warps done reading Hh -> staging may overwrite

        // ---- epilogue2: two coalesced passes via smem staging ----
        #pragma unroll
        for (int mt = 0; mt < 2; mt++) {
            // stage Wraw = D2 + b2 (fp32), compact rows cr = rt*16+g (+8)
            {
                int cr0 = rt * 16 + g;
                #pragma unroll
                for (int j = 0; j < 8; j++) {
                    int c = nh * 64 + j * 8 + tg * 2;
                    float bx = b2s[c], by = b2s[c + 1];
                    *(float2*)(Wst + (size_t)cr0 * SW + c) =
                        make_float2(acc[mt][j][0] + bx, acc[mt][j][1] + by);
                    *(float2*)(Wst + (size_t)(cr0 + 8) * SW + c) =
                        make_float2(acc[mt][j][2] + bx, acc[mt][j][3] + by);
                }
            }
            __syncthreads();
            // scatter: warp wid owns compact rows wid*8 .. wid*8+7 (one edge each)
            {
                int rowi[8], coli[8];
                float Ci[8];
                #pragma unroll
                for (int q = 0; q < 8; q++) {
                    int cr = wid * 8 + q;
                    int er = (cr >> 4) * 32 + mt * 16 + (cr & 15);
                    int e = e0 + er;
                    rowi[q] = ei[e];
                    coli[q] = ei[N_EDGES + e];
                    Ci[q]   = g_Cc[e];
                }
                #pragma unroll
                for (int q = 0; q < 8; q++) {
                    int cr = wid * 8 + q;
                    float4 xv = *(const float4*)(g_xh + (size_t)rowi[q] * HID + lane * 4);
                    float4 wv = *(const float4*)(Wst + (size_t)cr * SW + lane * 4);
                    float C = Ci[q];
                    float m0 = wv.x * C * xv.x;
                    float m1 = wv.y * C * xv.y;
                    float m2 = wv.z * C * xv.z;
                    float m3 = wv.w * C * xv.w;
                    asm volatile("red.global.add.v4.f32 [%0], {%1, %2, %3, %4};"
                                 :: "l"(g_agg + (size_t)coli[q] * HID + lane * 4),
                                    "f"(m0), "f"(m1), "f"(m2), "f"(m3) : "memory");
                }
            }
            __syncthreads();
        }
        // loop-end: last sync also protects A/Wst for next iteration
    }
}

// ---------------- node phase via fp16 mma ----------------
template <int LAST>
__global__ void __launch_bounds__(256, 1)
node_mma(const float* __restrict__ wA, const float* __restrict__ bA,
         const float* __restrict__ wB, const float* __restrict__ bB,
         const float* __restrict__ wC,
         const float* __restrict__ o1b, const float* __restrict__ o2w,
         const float* __restrict__ o2b,
         const int* __restrict__ batch, float* __restrict__ out) {
    extern __shared__ char smem[];
    half* WAh = (half*)(smem + NM_WA);
    half* WBh = (half*)(smem + NM_WB);
    half* WCh = (half*)(smem + NM_WC);
    half* Ah  = (half*)(smem + NM_AT);
    half* Hh  = (half*)(smem + NM_HT);
    float* bAs = (float*)(smem + NM_BA);
    float* bBs = (float*)(smem + NM_BB);
    float* BOs = (float*)(smem + NM_BO);
    float* O2s = (float*)(smem + NM_O2);

    const int tid = threadIdx.x, wid = tid >> 5, lane = tid & 31;
    const int g = lane >> 2, tg = lane & 3;
    const int rt = wid & 3, nh = wid >> 2;

    for (int i = tid; i < 128 * 128; i += 256) {
        int n = i >> 7, k = i & 127;
        WAh[n * SA2 + k] = __float2half_rn(wA[k * HID + n]);
        WBh[n * SA2 + k] = __float2half_rn(wB[k * HID + n]);
    }
    if (LAST) {
        for (int i = tid; i < 64 * 128; i += 256) {
            int n = i >> 7, k = i & 127;
            WCh[n * SA2 + k] = __float2half_rn(wC[k * 64 + n]);
        }
        if (tid < 64) { BOs[tid] = o1b[tid]; O2s[tid] = o2w[tid]; }
    } else {
        for (int i = tid; i < 128 * 128; i += 256) {
            int n = i >> 7, k = i & 127;
            WCh[n * SA2 + k] = __float2half_rn(wC[k * HID + n]);
        }
    }
    if (tid < HID) { bAs[tid] = bA[tid]; bBs[tid] = bB[tid]; }

    const uint32_t aU  = smem_to_u32(Ah);
    const uint32_t hU  = smem_to_u32(Hh);
    const uint32_t wAU = smem_to_u32(WAh);
    const uint32_t wBU = smem_to_u32(WBh);
    const uint32_t wCU = smem_to_u32(WCh);
    const int lrow = lane & 15;
    const int lkh  = (lane >> 4) << 3;
    const float ob = LAST ? o2b[0] : 0.f;

    for (int t = blockIdx.x; t < NT_TILES; t += gridDim.x) {
        const int n0 = t * 128;
        for (int i = tid; i < 128 * 32; i += 256) {
            int row = i >> 5, c4 = i & 31;
            float4* ap = (float4*)(g_agg + (size_t)(n0 + row) * HID) + c4;
            float4 v = *ap;
            *ap = make_float4(0.f, 0.f, 0.f, 0.f);
            half2 h0 = __floats2half2_rn(v.x, v.y);
            half2 h1 = __floats2half2_rn(v.z, v.w);
            *(uint2*)(Ah + (size_t)row * SA2 + c4 * 4) =
                make_uint2(*(uint32_t*)&h0, *(uint32_t*)&h1);
        }
        __syncthreads();

        float acc[2][8][4];
        #pragma unroll
        for (int mt = 0; mt < 2; mt++)
            #pragma unroll
            for (int j = 0; j < 8; j++)
                #pragma unroll
                for (int q = 0; q < 4; q++) acc[mt][j][q] = 0.f;
        #pragma unroll
        for (int ks = 0; ks < 8; ks++) {
            const int k0 = ks * 16;
            uint32_t am[2][4];
            #pragma unroll
            for (int mt = 0; mt < 2; mt++) {
                uint32_t addr = aU + (uint32_t)(((rt * 32 + mt * 16 + lrow) * SA2 + k0 + lkh) << 1);
                ldm_x4(am[mt][0], am[mt][1], am[mt][2], am[mt][3], addr);
            }
            #pragma unroll
            for (int jj = 0; jj < 4; jj++) {
                uint32_t b0, b1r, b2r, b3;
                uint32_t addr = wAU + (uint32_t)(((nh * 64 + jj * 16 + lrow) * SA2 + k0 + lkh) << 1);
                ldm_x4(b0, b1r, b2r, b3, addr);
                #pragma unroll
                for (int mt = 0; mt < 2; mt++) {
                    mma16816(acc[mt][2 * jj],     am[mt][0], am[mt][1], am[mt][2], am[mt][3], b0,  b2r);
                    mma16816(acc[mt][2 * jj + 1], am[mt][0], am[mt][1], am[mt][2], am[mt][3], b1r, b3);
                }
            }
        }
        #pragma unroll
        for (int mt = 0; mt < 2; mt++) {
            int r0 = rt * 32 + mt * 16 + g;
            #pragma unroll
            for (int j = 0; j < 8; j++) {
                int c = nh * 64 + j * 8 + tg * 2;
                float bx = bAs[c], by = bAs[c + 1];
                *(half2*)(Hh + (size_t)r0 * SA2 + c) =
                    __floats2half2_rn(sspf(acc[mt][j][0] + bx), sspf(acc[mt][j][1] + by));
                *(half2*)(Hh + (size_t)(r0 + 8) * SA2 + c) =
                    __floats2half2_rn(sspf(acc[mt][j][2] + bx), sspf(acc[mt][j][3] + by));
            }
        }
        __syncthreads();

        #pragma unroll
        for (int mt = 0; mt < 2; mt++)
            #pragma unroll
            for (int j = 0; j < 8; j++)
                #pragma unroll
                for (int q = 0; q < 4; q++) acc[mt][j][q] = 0.f;
        #pragma unroll
        for (int ks = 0; ks < 8; ks++) {
            const int k0 = ks * 16;
            uint32_t am[2][4];
            #pragma unroll
            for (int mt = 0; mt < 2; mt++) {
                uint32_t addr = hU + (uint32_t)(((rt * 32 + mt * 16 + lrow) * SA2 + k0 + lkh) << 1);
                ldm_x4(am[mt][0], am[mt][1], am[mt][2], am[mt][3], addr);
            }
            #pragma unroll
            for (int jj = 0; jj < 4; jj++) {
                uint32_t b0, b1r, b2r, b3;
                uint32_t addr = wBU + (uint32_t)(((nh * 64 + jj * 16 + lrow) * SA2 + k0 + lkh) << 1);
                ldm_x4(b0, b1r, b2r, b3, addr);
                #pragma unroll
                for (int mt = 0; mt < 2; mt++) {
                    mma16816(acc[mt][2 * jj],     am[mt][0], am[mt][1], am[mt][2], am[mt][3], b0,  b2r);
                    mma16816(acc[mt][2 * jj + 1], am[mt][0], am[mt][1], am[mt][2], am[mt][3], b1r, b3);
                }
            }
        }
        #pragma unroll
        for (int mt = 0; mt < 2; mt++) {
            int r0 = rt * 32 + mt * 16 + g;
            int gr0 = n0 + r0;
            #pragma unroll
            for (int j = 0; j < 8; j++) {
                int c = nh * 64 + j * 8 + tg * 2;
                float bx = bBs[c], by = bBs[c + 1];
                float2 h0 = *(const float2*)(g_h + (size_t)gr0 * HID + c);
                float2 h1 = *(const float2*)(g_h + (size_t)(gr0 + 8) * HID + c);
                float n00 = acc[mt][j][0] + bx + h0.x;
                float n01 = acc[mt][j][1] + by + h0.y;
                float n10 = acc[mt][j][2] + bx + h1.x;
                float n11 = acc[mt][j][3] + by + h1.y;
                if (!LAST) {
                    *(float2*)(g_h + (size_t)gr0 * HID + c)       = make_float2(n00, n01);
                    *(float2*)(g_h + (size_t)(gr0 + 8) * HID + c) = make_float2(n10, n11);
                }
                *(half2*)(Ah + (size_t)r0 * SA2 + c)       = __floats2half2_rn(n00, n01);
                *(half2*)(Ah + (size_t)(r0 + 8) * SA2 + c) = __floats2half2_rn(n10, n11);
            }
        }
        __syncthreads();

        const int NJ3 = LAST ? 2 : 4;
        #pragma unroll
        for (int mt = 0; mt < 2; mt++)
            #pragma unroll
            for (int j = 0; j < 8; j++)
                #pragma unroll
                for (int q = 0; q < 4; q++) acc[mt][j][q] = 0.f;
        #pragma unroll
        for (int ks = 0; ks < 8; ks++) {
            const int k0 = ks * 16;
            uint32_t am[2][4];
            #pragma unroll
            for (int mt = 0; mt < 2; mt++) {
                uint32_t addr = aU + (uint32_t)(((rt * 32 + mt * 16 + lrow) * SA2 + k0 + lkh) << 1);
                ldm_x4(am[mt][0], am[mt][1], am[mt][2], am[mt][3], addr);
            }
            #pragma unroll
            for (int jj = 0; jj < 4; jj++) {
                if (jj >= NJ3) break;
                uint32_t b0, b1r, b2r, b3;
                int ncol = LAST ? (nh * 32 + jj * 16) : (nh * 64 + jj * 16);
                uint32_t addr = wCU + (uint32_t)(((ncol + lrow) * SA2 + k0 + lkh) << 1);
                ldm_x4(b0, b1r, b2r, b3, addr);
                #pragma unroll
                for (int mt = 0; mt < 2; mt++) {
                    mma16816(acc[mt][2 * jj],     am[mt][0], am[mt][1], am[mt][2], am[mt][3], b0,  b2r);
                    mma16816(acc[mt][2 * jj + 1], am[mt][0], am[mt][1], am[mt][2], am[mt][3], b1r, b3);
                }
            }
        }
        if (!LAST) {
            #pragma unroll
            for (int mt = 0; mt < 2; mt++) {
                int gr0 = n0 + rt * 32 + mt * 16 + g;
                #pragma unroll
                for (int j = 0; j < 8; j++) {
                    int c = nh * 64 + j * 8 + tg * 2;
                    *(float2*)(g_xh + (size_t)gr0 * HID + c) =
                        make_float2(acc[mt][j][0], acc[mt][j][1]);
                    *(float2*)(g_xh + (size_t)(gr0 + 8) * HID + c) =
                        make_float2(acc[mt][j][2], acc[mt][j][3]);
                }
            }
        } else {
            #pragma unroll
            for (int mt = 0; mt < 2; mt++) {
                float s0 = 0.f, s1 = 0.f;
                #pragma unroll
                for (int j = 0; j < 4; j++) {
                    int c = nh * 32 + j * 8 + tg * 2;
                    float bx = BOs[c], by = BOs[c + 1];
                    float wx = O2s[c], wy = O2s[c + 1];
                    s0 += sspf(acc[mt][j][0] + bx) * wx + sspf(acc[mt][j][1] + by) * wy;
                    s1 += sspf(acc[mt][j][2] + bx) * wx + sspf(acc[mt][j][3] + by) * wy;
                }
                s0 += __shfl_xor_sync(0xffffffffu, s0, 1);
                s0 += __shfl_xor_sync(0xffffffffu, s0, 2);
                s1 += __shfl_xor_sync(0xffffffffu, s1, 1);
                s1 += __shfl_xor_sync(0xffffffffu, s1, 2);
                if (tg == 0) {
                    int rowA = n0 + rt * 32 + mt * 16 + g;
                    int rowB = rowA + 8;
                    float add = (nh == 0) ? ob : 0.f;
                    if (rowA < N_NODES) atomicAdd(&out[batch[rowA]], s0 + add);
                    if (rowB < N_NODES) atomicAdd(&out[batch[rowB]], s1 + add);
                }
            }
        }
        __syncthreads();
    }
}

// ---------------- launch ----------------
extern "C" void kernel_launch(void* const* d_in, const int* in_sizes, int n_in,
                              void* d_out, int out_size) {
    const int*   z      = (const int*)  d_in[0];
    const float* pos    = (const float*)d_in[1];
    const int*   batch  = (const int*)  d_in[2];
    const int*   ei     = (const int*)  d_in[3];
    const float* eattr  = (const float*)d_in[4];
    const float* emb    = (const float*)d_in[5];
    const float* mlp_w1 = (const float*)d_in[6];
    const float* mlp_b1 = (const float*)d_in[7];
    const float* mlp_w2 = (const float*)d_in[8];
    const float* mlp_b2 = (const float*)d_in[9];
    const float* cf1_w  = (const float*)d_in[10];
    const float* cf2_w  = (const float*)d_in[11];
    const float* cf2_b  = (const float*)d_in[12];
    const float* lin_w  = (const float*)d_in[13];
    const float* lin_b  = (const float*)d_in[14];
    const float* o1w    = (const float*)d_in[15];
    const float* o1b    = (const float*)d_in[16];
    const float* o2w    = (const float*)d_in[17];
    const float* o2b    = (const float*)d_in[18];
    float* out = (float*)d_out;

    const int NI_SMEM = (HID * HID + 8 * 512) * (int)sizeof(float);
    cudaFuncSetAttribute(edge_mma_kernel, cudaFuncAttributeMaxDynamicSharedMemorySize, EK_SMEM);
    cudaFuncSetAttribute(node_init,   cudaFuncAttributeMaxDynamicSharedMemorySize, NI_SMEM);
    cudaFuncSetAttribute(node_mma<0>, cudaFuncAttributeMaxDynamicSharedMemorySize, NM_SMEM);
    cudaFuncSetAttribute(node_mma<1>, cudaFuncAttributeMaxDynamicSharedMemorySize, NM_SMEM);

    zero_out_kernel<<<1, 32>>>(out);
    edge_pre_kernel<<<(2 * N_EDGES + 255) / 256, 256>>>(ei, pos, eattr);
    node_init<<<296, 256, NI_SMEM>>>(z, emb, cf1_w);

    for (int l = 0; l < 3; l++) {
        edge_mma_kernel<<<296, 256, EK_SMEM>>>(ei,
                                               mlp_w1 + (size_t)l * NF * HID, mlp_b1 + (size_t)l * HID,
                                               mlp_w2 + (size_t)l * HID * HID, mlp_b2 + (size_t)l * HID);
        if (l < 2) {
            node_mma<0><<<148, 256, NM_SMEM>>>(
                cf2_w + (size_t)l * HID * HID, cf2_b + (size_t)l * HID,
                lin_w + (size_t)l * HID * HID, lin_b + (size_t)l * HID,
                cf1_w + (size_t)(l + 1) * HID * HID,
                nullptr, nullptr, nullptr, batch, out);
        } else {
            node_mma<1><<<148, 256, NM_SMEM>>>(
                cf2_w + (size_t)l * HID * HID, cf2_b + (size_t)l * HID,
                lin_w + (size_t)l * HID * HID, lin_b + (size_t)l * HID,
                o1w, o1b, o2w, o2b, batch, out);
        }
    }
}

// round 9
// speedup vs baseline: 6.4415x; 1.0165x over previous
#include <cuda_runtime.h>
#include <cuda_fp16.h>
#include <cstdint>
#include <math.h>

#define N_NODES 20000
#define N_PAD   20096            // 157 * 128
#define NT_TILES 157
#define N_EDGES 640000
#define HID 128
#define NB 3
#define NGS 47
#define NF 50
#define B_GRAPHS 16
#define LOG2F_ 0.69314718055994530942f
#define CUTF 10.0f
#define PI_F 3.14159265358979323846f
#define EDGE_TILES (N_EDGES / 128)   // 5000

#define SA1 72     // halves stride for A / W1 tiles (K=64 + 8 pad)
#define SA2 136    // halves stride for K=128 tiles (+8 pad)
#define SW  136    // float stride for staged W tile (64 rows)

// ---- edge kernel smem byte offsets ----
#define OFF_W1h 0                         // 18432
#define OFF_W2h 18432                     // 34816
#define OFF_A   53248                     // 18432
#define OFF_H   71680                     // 34816 (also fp32 W staging)
#define OFF_B1  106496                    // 512
#define OFF_B2  107008                    // 512
#define EK_SMEM 107520                    // 2 CTAs/SM

// ---- node kernel smem byte offsets ----
#define NM_WA  0
#define NM_WB  34816
#define NM_WC  69632
#define NM_AT  104448
#define NM_HT  139264
#define NM_BA  174080
#define NM_BB  174592
#define NM_BO  175104
#define NM_O2  175360
#define NM_SMEM 175616

// ---------------- scratch ----------------
__device__ float g_h  [N_PAD * HID];
__device__ float g_xh [N_PAD * HID];
__device__ float g_agg[N_PAD * HID];
__device__ float g_Cc [N_EDGES];
__device__ half  g_feat[(size_t)N_EDGES * 64];

__device__ __forceinline__ float sspf(float x) {
    float e = __expf(-fabsf(x));
    return fmaxf(x, 0.f) + __logf(1.f + e) - LOG2F_;
}
__device__ __forceinline__ uint32_t smem_to_u32(const void* p) {
    uint32_t a;
    asm("{ .reg .u64 t; cvta.to.shared.u64 t, %1; cvt.u32.u64 %0, t; }" : "=r"(a) : "l"(p));
    return a;
}
__device__ __forceinline__ void ldm_x4(uint32_t& r0, uint32_t& r1, uint32_t& r2, uint32_t& r3, uint32_t a) {
    asm volatile("ldmatrix.sync.aligned.m8n8.x4.shared.b16 {%0,%1,%2,%3}, [%4];"
                 : "=r"(r0), "=r"(r1), "=r"(r2), "=r"(r3) : "r"(a));
}
__device__ __forceinline__ void mma16816(float* c, uint32_t a0, uint32_t a1, uint32_t a2, uint32_t a3,
                                         uint32_t b0, uint32_t b1) {
    asm volatile("mma.sync.aligned.m16n8k16.row.col.f32.f16.f16.f32 "
                 "{%0,%1,%2,%3}, {%4,%5,%6,%7}, {%8,%9}, {%0,%1,%2,%3};"
                 : "+f"(c[0]), "+f"(c[1]), "+f"(c[2]), "+f"(c[3])
                 : "r"(a0), "r"(a1), "r"(a2), "r"(a3), "r"(b0), "r"(b1));
}

// ---------------- small kernels ----------------
__global__ void zero_out_kernel(float* out) {
    if (threadIdx.x < B_GRAPHS) out[threadIdx.x] = 0.f;
}

// edge_pre: one thread per edge; gaussians via 2-exp recurrence.
__global__ void edge_pre_kernel(const int* __restrict__ ei, const float* __restrict__ pos,
                                const float* __restrict__ eattr) {
    int e = blockIdx.x * blockDim.x + threadIdx.x;
    if (e >= N_EDGES) return;
    int r = ei[e], c = ei[N_EDGES + e];
    float dx = pos[r * 3 + 0] - pos[c * 3 + 0];
    float dy = pos[r * 3 + 1] - pos[c * 3 + 1];
    float dz = pos[r * 3 + 2] - pos[c * 3 + 2];
    float ew = sqrtf(dx * dx + dy * dy + dz * dz);
    g_Cc[e] = 0.5f * (cosf(ew * (PI_F / CUTF)) + 1.f);

    const float step = CUTF / (float)(NGS - 1);
    float fv[64];
    fv[0] = eattr[e * NB + 0];
    fv[1] = eattr[e * NB + 1];
    fv[2] = eattr[e * NB + 2];
    // gs_k = exp(-0.5*((ew - k*step)/step)^2); ratio gs_{k+1}/gs_k = exp(u - 0.5 - k)
    float u  = ew / step;
    float gs = __expf(-0.5f * u * u);
    float m  = __expf(u - 0.5f);
    const float d = 0.36787944117144233f;   // e^-1
    fv[3] = gs;
    #pragma unroll
    for (int k = 1; k < NGS; k++) {
        gs *= m;
        m  *= d;
        fv[3 + k] = gs;
    }
    #pragma unroll
    for (int k = NF; k < 64; k++) fv[k] = 0.f;

    half2 tmp[32];
    #pragma unroll
    for (int j = 0; j < 32; j++) tmp[j] = __floats2half2_rn(fv[2 * j], fv[2 * j + 1]);
    uint4* dst = (uint4*)(g_feat + (size_t)e * 64);
    #pragma unroll
    for (int j = 0; j < 8; j++) dst[j] = ((uint4*)tmp)[j];
}

// ---------------- node_init ----------------
__global__ void __launch_bounds__(256)
node_init(const int* __restrict__ z, const float* __restrict__ emb,
          const float* __restrict__ W) {
    extern __shared__ float sm[];
    float* Ws = sm;
    float* xs = Ws + HID * HID;
    for (int i = threadIdx.x; i < HID * HID; i += blockDim.x) Ws[i] = W[i];
    __syncthreads();

    const int wid = threadIdx.x >> 5, lane = threadIdx.x & 31;
    float* xw = xs + wid * 512;
    const int gw = blockIdx.x * 8 + wid, nw = gridDim.x * 8;
    const int c0 = lane * 4;

    for (int gidx = gw; gidx < N_PAD / 4; gidx += nw) {
        int n0 = gidx * 4;
        #pragma unroll
        for (int j = 0; j < 4; j++) {
            int nn = n0 + j;
            float4 v = make_float4(0.f, 0.f, 0.f, 0.f);
            if (nn < N_NODES) {
                int zr = z[nn];
                v = ((const float4*)(emb + (size_t)zr * HID))[lane];
            }
            ((float4*)xw)[lane + 32 * j] = v;
            ((float4*)(g_h + (size_t)nn * HID))[lane] = v;
            ((float4*)(g_agg + (size_t)nn * HID))[lane] = make_float4(0.f, 0.f, 0.f, 0.f);
        }
        __syncwarp();
        float a[4][4];
        #pragma unroll
        for (int r = 0; r < 4; r++) { a[r][0] = a[r][1] = a[r][2] = a[r][3] = 0.f; }
        #pragma unroll 4
        for (int k = 0; k < HID; k++) {
            float4 w = *(const float4*)(Ws + k * HID + c0);
            #pragma unroll
            for (int r = 0; r < 4; r++) {
                float v = xw[r * HID + k];
                a[r][0] += v * w.x; a[r][1] += v * w.y; a[r][2] += v * w.z; a[r][3] += v * w.w;
            }
        }
        #pragma unroll
        for (int r = 0; r < 4; r++)
            *(float4*)(g_xh + (size_t)(n0 + r) * HID + c0) =
                make_float4(a[r][0], a[r][1], a[r][2], a[r][3]);
        __syncwarp();
    }
}

// ---------------- edge filter MLP (unchanged from R8) ----------------
__global__ void __launch_bounds__(256, 2)
edge_mma_kernel(const int* __restrict__ ei,
                const float* __restrict__ w1, const float* __restrict__ b1,
                const float* __restrict__ w2, const float* __restrict__ b2) {
    extern __shared__ char smem[];
    half* w1h = (half*)(smem + OFF_W1h);
    half* w2h = (half*)(smem + OFF_W2h);
    half* Ah  = (half*)(smem + OFF_A);
    half* Hh  = (half*)(smem + OFF_H);
    float* Wst = (float*)(smem + OFF_H);
    float* b1s = (float*)(smem + OFF_B1);
    float* b2s = (float*)(smem + OFF_B2);

    const int tid = threadIdx.x, wid = tid >> 5, lane = tid & 31;
    const int g = lane >> 2, tg = lane & 3;
    const int rt = wid & 3, nh = wid >> 2;
    const int aedge = tid >> 1, aseg = tid & 1;

    for (int i = tid; i < 128 * 64; i += 256) {
        int n = i >> 6, k = i & 63;
        w1h[n * SA1 + k] = __float2half_rn((k < NF) ? w1[k * HID + n] : 0.f);
    }
    for (int i = tid; i < 128 * 128; i += 256) {
        int n = i >> 7, k = i & 127;
        w2h[n * SA2 + k] = __float2half_rn(w2[k * HID + n]);
    }
    if (tid < HID) { b1s[tid] = b1[tid]; b2s[tid] = b2[tid]; }

    const uint32_t aU  = smem_to_u32(Ah);
    const uint32_t hU  = smem_to_u32(Hh);
    const uint32_t w1U = smem_to_u32(w1h);
    const uint32_t w2U = smem_to_u32(w2h);
    const int lrow = lane & 15;
    const int lkh  = (lane >> 4) << 3;

    uint4* aDst = (uint4*)(Ah + aedge * SA1 + aseg * 32);
    {
        const uint4* src = (const uint4*)(g_feat + ((size_t)blockIdx.x * 128 + aedge) * 64 + aseg * 32);
        #pragma unroll
        for (int j = 0; j < 4; j++) aDst[j] = src[j];
    }
    __syncthreads();

    for (int t = blockIdx.x; t < EDGE_TILES; t += gridDim.x) {
        const int e0 = t * 128;
        float acc[2][8][4];
        #pragma unroll
        for (int mt = 0; mt < 2; mt++)
            #pragma unroll
            for (int j = 0; j < 8; j++)
                #pragma unroll
                for (int q = 0; q < 4; q++) acc[mt][j][q] = 0.f;

        // ---- GEMM1 ----
        #pragma unroll
        for (int ks = 0; ks < 4; ks++) {
            const int k0 = ks * 16;
            uint32_t am[2][4];
            #pragma unroll
            for (int mt = 0; mt < 2; mt++) {
                uint32_t addr = aU + (uint32_t)(((rt * 32 + mt * 16 + lrow) * SA1 + k0 + lkh) << 1);
                ldm_x4(am[mt][0], am[mt][1], am[mt][2], am[mt][3], addr);
            }
            #pragma unroll
            for (int jj = 0; jj < 4; jj++) {
                uint32_t b0, b1r, b2r, b3;
                uint32_t addr = w1U + (uint32_t)(((nh * 64 + jj * 16 + lrow) * SA1 + k0 + lkh) << 1);
                ldm_x4(b0, b1r, b2r, b3, addr);
                #pragma unroll
                for (int mt = 0; mt < 2; mt++) {
                    mma16816(acc[mt][2 * jj],     am[mt][0], am[mt][1], am[mt][2], am[mt][3], b0,  b2r);
                    mma16816(acc[mt][2 * jj + 1], am[mt][0], am[mt][1], am[mt][2], am[mt][3], b1r, b3);
                }
            }
        }
        __syncthreads();

        // ---- epilogue1: H = fp16(ssp(D1 + b1)) ----
        #pragma unroll
        for (int mt = 0; mt < 2; mt++) {
            int r0 = rt * 32 + mt * 16 + g;
            #pragma unroll
            for (int j = 0; j < 8; j++) {
                int c = nh * 64 + j * 8 + tg * 2;
                float bx = b1s[c], by = b1s[c + 1];
                *(half2*)(Hh + (size_t)r0 * SA2 + c) =
                    __floats2half2_rn(sspf(acc[mt][j][0] + bx), sspf(acc[mt][j][1] + by));
                *(half2*)(Hh + (size_t)(r0 + 8) * SA2 + c) =
                    __floats2half2_rn(sspf(acc[mt][j][2] + bx), sspf(acc[mt][j][3] + by));
            }
        }

        uint4 ap[4];
        const int tn = t + gridDim.x;
        if (tn < EDGE_TILES) {
            const uint4* src = (const uint4*)(g_feat + ((size_t)tn * 128 + aedge) * 64 + aseg * 32);
            #pragma unroll
            for (int j = 0; j < 4; j++) ap[j] = src[j];
        }
        __syncthreads();

        // ---- GEMM2 ----
        #pragma unroll
        for (int mt = 0; mt < 2; mt++)
            #pragma unroll
            for (int j = 0; j < 8; j++)
                #pragma unroll
                for (int q = 0; q < 4; q++) acc[mt][j][q] = 0.f;
        #pragma unroll
        for (int ks = 0; ks < 8; ks++) {
            const int k0 = ks * 16;
            uint32_t am[2][4];
            #pragma unroll
            for (int mt = 0; mt < 2; mt++) {
                uint32_t addr = hU + (uint32_t)(((rt * 32 + mt * 16 + lrow) * SA2 + k0 + lkh) << 1);
                ldm_x4(am[mt][0], am[mt][1], am[mt][2], am[mt][3], addr);
            }
            #pragma unroll
            for (int jj = 0; jj < 4; jj++) {
                uint32_t b0, b1r, b2r, b3;
                uint32_t addr = w2U + (uint32_t)(((nh * 64 + jj * 16 + lrow) * SA2 + k0 + lkh) << 1);
                ldm_x4(b0, b1r, b2r, b3, addr);
                #pragma unroll
                for (int mt = 0; mt < 2; mt++) {
                    mma16816(acc[mt][2 * jj],     am[mt][0], am[mt][1], am[mt][2], am[mt][3], b0,  b2r);
                    mma16816(acc[mt][2 * jj + 1], am[mt][0], am[mt][1], am[mt][2], am[mt][3], b1r, b3);
                }
            }
        }

        if (tn < EDGE_TILES) {
            #pragma unroll
            for (int j = 0; j < 4; j++) aDst[j] = ap[j];
        }
        __syncthreads();

        // ---- epilogue2: staged coalesced scatter ----
        #pragma unroll
        for (int mt = 0; mt < 2; mt++) {
            {
                int cr0 = rt * 16 + g;
                #pragma unroll
                for (int j = 0; j < 8; j++) {
                    int c = nh * 64 + j * 8 + tg * 2;
                    float bx = b2s[c], by = b2s[c + 1];
                    *(float2*)(Wst + (size_t)cr0 * SW + c) =
                        make_float2(acc[mt][j][0] + bx, acc[mt][j][1] + by);
                    *(float2*)(Wst + (size_t)(cr0 + 8) * SW + c) =
                        make_float2(acc[mt][j][2] + bx, acc[mt][j][3] + by);
                }
            }
            __syncthreads();
            {
                int rowi[8], coli[8];
                float Ci[8];
                #pragma unroll
                for (int q = 0; q < 8; q++) {
                    int cr = wid * 8 + q;
                    int er = (cr >> 4) * 32 + mt * 16 + (cr & 15);
                    int e = e0 + er;
                    rowi[q] = ei[e];
                    coli[q] = ei[N_EDGES + e];
                    Ci[q]   = g_Cc[e];
                }
                #pragma unroll
                for (int q = 0; q < 8; q++) {
                    int cr = wid * 8 + q;
                    float4 xv = *(const float4*)(g_xh + (size_t)rowi[q] * HID + lane * 4);
                    float4 wv = *(const float4*)(Wst + (size_t)cr * SW + lane * 4);
                    float C = Ci[q];
                    float m0 = wv.x * C * xv.x;
                    float m1 = wv.y * C * xv.y;
                    float m2 = wv.z * C * xv.z;
                    float m3 = wv.w * C * xv.w;
                    asm volatile("red.global.add.v4.f32 [%0], {%1, %2, %3, %4};"
                                 :: "l"(g_agg + (size_t)coli[q] * HID + lane * 4),
                                    "f"(m0), "f"(m1), "f"(m2), "f"(m3) : "memory");
                }
            }
            __syncthreads();
        }
    }
}

// ---------------- node phase via fp16 mma, 512 threads ----------------
// warp layout: rt = wid&7 (16-row tiles), nh = wid>>3 (64-col halves)
template <int LAST>
__global__ void __launch_bounds__(512, 1)
node_mma(const float* __restrict__ wA, const float* __restrict__ bA,
         const float* __restrict__ wB, const float* __restrict__ bB,
         const float* __restrict__ wC,
         const float* __restrict__ o1b, const float* __restrict__ o2w,
         const float* __restrict__ o2b,
         const int* __restrict__ batch, float* __restrict__ out) {
    extern __shared__ char smem[];
    half* WAh = (half*)(smem + NM_WA);
    half* WBh = (half*)(smem + NM_WB);
    half* WCh = (half*)(smem + NM_WC);
    half* Ah  = (half*)(smem + NM_AT);
    half* Hh  = (half*)(smem + NM_HT);
    float* bAs = (float*)(smem + NM_BA);
    float* bBs = (float*)(smem + NM_BB);
    float* BOs = (float*)(smem + NM_BO);
    float* O2s = (float*)(smem + NM_O2);

    const int tid = threadIdx.x, wid = tid >> 5, lane = tid & 31;
    const int g = lane >> 2, tg = lane & 3;
    const int rt = wid & 7, nh = wid >> 3;

    for (int i = tid; i < 128 * 128; i += 512) {
        int n = i >> 7, k = i & 127;
        WAh[n * SA2 + k] = __float2half_rn(wA[k * HID + n]);
        WBh[n * SA2 + k] = __float2half_rn(wB[k * HID + n]);
    }
    if (LAST) {
        for (int i = tid; i < 64 * 128; i += 512) {
            int n = i >> 7, k = i & 127;
            WCh[n * SA2 + k] = __float2half_rn(wC[k * 64 + n]);
        }
        if (tid < 64) { BOs[tid] = o1b[tid]; O2s[tid] = o2w[tid]; }
    } else {
        for (int i = tid; i < 128 * 128; i += 512) {
            int n = i >> 7, k = i & 127;
            WCh[n * SA2 + k] = __float2half_rn(wC[k * HID + n]);
        }
    }
    if (tid < HID) { bAs[tid] = bA[tid]; bBs[tid] = bB[tid]; }

    const uint32_t aU  = smem_to_u32(Ah);
    const uint32_t hU  = smem_to_u32(Hh);
    const uint32_t wAU = smem_to_u32(WAh);
    const uint32_t wBU = smem_to_u32(WBh);
    const uint32_t wCU = smem_to_u32(WCh);
    const int lrow = lane & 15;
    const int lkh  = (lane >> 4) << 3;
    const float ob = LAST ? o2b[0] : 0.f;

    for (int t = blockIdx.x; t < NT_TILES; t += gridDim.x) {
        const int n0 = t * 128;
        // A = fp16(agg), zero agg
        for (int i = tid; i < 128 * 32; i += 512) {
            int row = i >> 5, c4 = i & 31;
            float4* ap = (float4*)(g_agg + (size_t)(n0 + row) * HID) + c4;
            float4 v = *ap;
            *ap = make_float4(0.f, 0.f, 0.f, 0.f);
            half2 h0 = __floats2half2_rn(v.x, v.y);
            half2 h1 = __floats2half2_rn(v.z, v.w);
            *(uint2*)(Ah + (size_t)row * SA2 + c4 * 4) =
                make_uint2(*(uint32_t*)&h0, *(uint32_t*)&h1);
        }
        __syncthreads();

        float acc[8][4];
        // ---- GEMM1: A @ WA ----
        #pragma unroll
        for (int j = 0; j < 8; j++)
            #pragma unroll
            for (int q = 0; q < 4; q++) acc[j][q] = 0.f;
        #pragma unroll
        for (int ks = 0; ks < 8; ks++) {
            const int k0 = ks * 16;
            uint32_t am[4];
            uint32_t addr = aU + (uint32_t)(((rt * 16 + lrow) * SA2 + k0 + lkh) << 1);
            ldm_x4(am[0], am[1], am[2], am[3], addr);
            #pragma unroll
            for (int jj = 0; jj < 4; jj++) {
                uint32_t b0, b1r, b2r, b3;
                uint32_t baddr = wAU + (uint32_t)(((nh * 64 + jj * 16 + lrow) * SA2 + k0 + lkh) << 1);
                ldm_x4(b0, b1r, b2r, b3, baddr);
                mma16816(acc[2 * jj],     am[0], am[1], am[2], am[3], b0,  b2r);
                mma16816(acc[2 * jj + 1], am[0], am[1], am[2], am[3], b1r, b3);
            }
        }
        // epi1: H = fp16(ssp(D1 + bA))
        {
            int r0 = rt * 16 + g;
            #pragma unroll
            for (int j = 0; j < 8; j++) {
                int c = nh * 64 + j * 8 + tg * 2;
                float bx = bAs[c], by = bAs[c + 1];
                *(half2*)(Hh + (size_t)r0 * SA2 + c) =
                    __floats2half2_rn(sspf(acc[j][0] + bx), sspf(acc[j][1] + by));
                *(half2*)(Hh + (size_t)(r0 + 8) * SA2 + c) =
                    __floats2half2_rn(sspf(acc[j][2] + bx), sspf(acc[j][3] + by));
            }
        }
        __syncthreads();

        // ---- GEMM2: H @ WB ----
        #pragma unroll
        for (int j = 0; j < 8; j++)
            #pragma unroll
            for (int q = 0; q < 4; q++) acc[j][q] = 0.f;
        #pragma unroll
        for (int ks = 0; ks < 8; ks++) {
            const int k0 = ks * 16;
            uint32_t am[4];
            uint32_t addr = hU + (uint32_t)(((rt * 16 + lrow) * SA2 + k0 + lkh) << 1);
            ldm_x4(am[0], am[1], am[2], am[3], addr);
            #pragma unroll
            for (int jj = 0; jj < 4; jj++) {
                uint32_t b0, b1r, b2r, b3;
                uint32_t baddr = wBU + (uint32_t)(((nh * 64 + jj * 16 + lrow) * SA2 + k0 + lkh) << 1);
                ldm_x4(b0, b1r, b2r, b3, baddr);
                mma16816(acc[2 * jj],     am[0], am[1], am[2], am[3], b0,  b2r);
                mma16816(acc[2 * jj + 1], am[0], am[1], am[2], am[3], b1r, b3);
            }
        }
        // epi2: hn = h + D2 + bB; residual store; A' = fp16(hn)
        {
            int r0 = rt * 16 + g;
            int gr0 = n0 + r0;
            #pragma unroll
            for (int j = 0; j < 8; j++) {
                int c = nh * 64 + j * 8 + tg * 2;
                float bx = bBs[c], by = bBs[c + 1];
                float2 h0 = *(const float2*)(g_h + (size_t)gr0 * HID + c);
                float2 h1 = *(const float2*)(g_h + (size_t)(gr0 + 8) * HID + c);
                float n00 = acc[j][0] + bx + h0.x;
                float n01 = acc[j][1] + by + h0.y;
                float n10 = acc[j][2] + bx + h1.x;
                float n11 = acc[j][3] + by + h1.y;
                if (!LAST) {
                    *(float2*)(g_h + (size_t)gr0 * HID + c)       = make_float2(n00, n01);
                    *(float2*)(g_h + (size_t)(gr0 + 8) * HID + c) = make_float2(n10, n11);
                }
                *(half2*)(Ah + (size_t)r0 * SA2 + c)       = __floats2half2_rn(n00, n01);
                *(half2*)(Ah + (size_t)(r0 + 8) * SA2 + c) = __floats2half2_rn(n10, n11);
            }
        }
        __syncthreads();

        // ---- GEMM3: A' @ WC ----
        const int NJ3 = LAST ? 2 : 4;
        #pragma unroll
        for (int j = 0; j < 8; j++)
            #pragma unroll
            for (int q = 0; q < 4; q++) acc[j][q] = 0.f;
        #pragma unroll
        for (int ks = 0; ks < 8; ks++) {
            const int k0 = ks * 16;
            uint32_t am[4];
            uint32_t addr = aU + (uint32_t)(((rt * 16 + lrow) * SA2 + k0 + lkh) << 1);
            ldm_x4(am[0], am[1], am[2], am[3], addr);
            #pragma unroll
            for (int jj = 0; jj < 4; jj++) {
                if (jj >= NJ3) break;
                uint32_t b0, b1r, b2r, b3;
                int ncol = LAST ? (nh * 32 + jj * 16) : (nh * 64 + jj * 16);
                uint32_t baddr = wCU + (uint32_t)(((ncol + lrow) * SA2 + k0 + lkh) << 1);
                ldm_x4(b0, b1r, b2r, b3, baddr);
                mma16816(acc[2 * jj],     am[0], am[1], am[2], am[3], b0,  b2r);
                mma16816(acc[2 * jj + 1], am[0], am[1], am[2], am[3], b1r, b3);
            }
        }
        if (!LAST) {
            int gr0 = n0 + rt * 16 + g;
            #pragma unroll
            for (int j = 0; j < 8; j++) {
                int c = nh * 64 + j * 8 + tg * 2;
                *(float2*)(g_xh + (size_t)gr0 * HID + c) =
                    make_float2(acc[j][0], acc[j][1]);
                *(float2*)(g_xh + (size_t)(gr0 + 8) * HID + c) =
                    make_float2(acc[j][2], acc[j][3]);
            }
        } else {
            float s0 = 0.f, s1 = 0.f;
            #pragma unroll
            for (int j = 0; j < 4; j++) {
                int c = nh * 32 + j * 8 + tg * 2;
                float bx = BOs[c], by = BOs[c + 1];
                float wx = O2s[c], wy = O2s[c + 1];
                s0 += sspf(acc[j][0] + bx) * wx + sspf(acc[j][1] + by) * wy;
                s1 += sspf(acc[j][2] + bx) * wx + sspf(acc[j][3] + by) * wy;
            }
            s0 += __shfl_xor_sync(0xffffffffu, s0, 1);
            s0 += __shfl_xor_sync(0xffffffffu, s0, 2);
            s1 += __shfl_xor_sync(0xffffffffu, s1, 1);
            s1 += __shfl_xor_sync(0xffffffffu, s1, 2);
            if (tg == 0) {
                int rowA = n0 + rt * 16 + g;
                int rowB = rowA + 8;
                float add = (nh == 0) ? ob : 0.f;
                if (rowA < N_NODES) atomicAdd(&out[batch[rowA]], s0 + add);
                if (rowB < N_NODES) atomicAdd(&out[batch[rowB]], s1 + add);
            }
        }
        __syncthreads();
    }
}

// ---------------- launch ----------------
extern "C" void kernel_launch(void* const* d_in, const int* in_sizes, int n_in,
                              void* d_out, int out_size) {
    const int*   z      = (const int*)  d_in[0];
    const float* pos    = (const float*)d_in[1];
    const int*   batch  = (const int*)  d_in[2];
    const int*   ei     = (const int*)  d_in[3];
    const float* eattr  = (const float*)d_in[4];
    const float* emb    = (const float*)d_in[5];
    const float* mlp_w1 = (const float*)d_in[6];
    const float* mlp_b1 = (const float*)d_in[7];
    const float* mlp_w2 = (const float*)d_in[8];
    const float* mlp_b2 = (const float*)d_in[9];
    const float* cf1_w  = (const float*)d_in[10];
    const float* cf2_w  = (const float*)d_in[11];
    const float* cf2_b  = (const float*)d_in[12];
    const float* lin_w  = (const float*)d_in[13];
    const float* lin_b  = (const float*)d_in[14];
    const float* o1w    = (const float*)d_in[15];
    const float* o1b    = (const float*)d_in[16];
    const float* o2w    = (const float*)d_in[17];
    const float* o2b    = (const float*)d_in[18];
    float* out = (float*)d_out;

    const int NI_SMEM = (HID * HID + 8 * 512) * (int)sizeof(float);
    cudaFuncSetAttribute(edge_mma_kernel, cudaFuncAttributeMaxDynamicSharedMemorySize, EK_SMEM);
    cudaFuncSetAttribute(node_init,   cudaFuncAttributeMaxDynamicSharedMemorySize, NI_SMEM);
    cudaFuncSetAttribute(node_mma<0>, cudaFuncAttributeMaxDynamicSharedMemorySize, NM_SMEM);
    cudaFuncSetAttribute(node_mma<1>, cudaFuncAttributeMaxDynamicSharedMemorySize, NM_SMEM);

    zero_out_kernel<<<1, 32>>>(out);
    edge_pre_kernel<<<(N_EDGES + 255) / 256, 256>>>(ei, pos, eattr);
    node_init<<<296, 256, NI_SMEM>>>(z, emb, cf1_w);

    for (int l = 0; l < 3; l++) {
        edge_mma_kernel<<<296, 256, EK_SMEM>>>(ei,
                                               mlp_w1 + (size_t)l * NF * HID, mlp_b1 + (size_t)l * HID,
                                               mlp_w2 + (size_t)l * HID * HID, mlp_b2 + (size_t)l * HID);
        if (l < 2) {
            node_mma<0><<<148, 512, NM_SMEM>>>(
                cf2_w + (size_t)l * HID * HID, cf2_b + (size_t)l * HID,
                lin_w + (size_t)l * HID * HID, lin_b + (size_t)l * HID,
                cf1_w + (size_t)(l + 1) * HID * HID,
                nullptr, nullptr, nullptr, batch, out);
        } else {
            node_mma<1><<<148, 512, NM_SMEM>>>(
                cf2_w + (size_t)l * HID * HID, cf2_b + (size_t)l * HID,
                lin_w + (size_t)l * HID * HID, lin_b + (size_t)l * HID,
                o1w, o1b, o2w, o2b, batch, out);
        }
    }
}